// round 1
// baseline (speedup 1.0000x reference)
#include <cuda_runtime.h>
#include <math.h>

#define BATCH  4
#define SLEN   2048
#define DMODEL 1024
#define NHEAD  16
#define DHEAD  64
#define ATT_SCALE 0.125f   // 1/sqrt(64)

// Scratch for projected q/k/v: [B, S, H, DHEAD] row-major = [B, S, DMODEL]
__device__ float g_q[BATCH * SLEN * DMODEL];
__device__ float g_k[BATCH * SLEN * DMODEL];
__device__ float g_v[BATCH * SLEN * DMODEL];

// ---------------------------------------------------------------------------
// Projection GEMM: Y[M=8192, N=1024] = X[M,K=1024] @ W[K,N] + bias
// 128x128 tile, BK=16, 8x8 per thread, 256 threads.
// ---------------------------------------------------------------------------
__global__ __launch_bounds__(256)
void proj_kernel(const float* __restrict__ X, const float* __restrict__ W,
                 const float* __restrict__ bias, float* __restrict__ Y)
{
    __shared__ float As[16][128];   // transposed A tile: As[k][m]
    __shared__ float Bs[16][128];   // Bs[k][n]

    const int tid = threadIdx.x;
    const int tx  = tid & 15;
    const int ty  = tid >> 4;
    const int m0  = blockIdx.y << 7;
    const int n0  = blockIdx.x << 7;

    const int arow = tid >> 2;           // 0..63
    const int acol = (tid & 3) << 2;     // 0,4,8,12
    const int brow = tid >> 5;           // 0..7
    const int bcol = (tid & 31) << 2;    // 0..124

    float acc[8][8];
#pragma unroll
    for (int i = 0; i < 8; i++)
#pragma unroll
        for (int j = 0; j < 8; j++) acc[i][j] = 0.f;

    const float* Xp = X + (size_t)(m0 + arow) * DMODEL + acol;
    const float* Wp = W + (size_t)brow * DMODEL + n0 + bcol;

    for (int k0 = 0; k0 < DMODEL; k0 += 16) {
        float4 a0 = *(const float4*)(Xp + k0);
        float4 a1 = *(const float4*)(Xp + k0 + (size_t)64 * DMODEL);
        float4 b0 = *(const float4*)(Wp + (size_t)k0 * DMODEL);
        float4 b1 = *(const float4*)(Wp + (size_t)(k0 + 8) * DMODEL);

        As[acol + 0][arow] = a0.x;  As[acol + 1][arow] = a0.y;
        As[acol + 2][arow] = a0.z;  As[acol + 3][arow] = a0.w;
        As[acol + 0][arow + 64] = a1.x;  As[acol + 1][arow + 64] = a1.y;
        As[acol + 2][arow + 64] = a1.z;  As[acol + 3][arow + 64] = a1.w;
        *(float4*)&Bs[brow][bcol]     = b0;
        *(float4*)&Bs[brow + 8][bcol] = b1;
        __syncthreads();

#pragma unroll
        for (int kk = 0; kk < 16; kk++) {
            float a[8], b[8];
            *(float4*)&a[0] = *(const float4*)&As[kk][ty * 8];
            *(float4*)&a[4] = *(const float4*)&As[kk][ty * 8 + 4];
            *(float4*)&b[0] = *(const float4*)&Bs[kk][tx * 8];
            *(float4*)&b[4] = *(const float4*)&Bs[kk][tx * 8 + 4];
#pragma unroll
            for (int i = 0; i < 8; i++)
#pragma unroll
                for (int j = 0; j < 8; j++)
                    acc[i][j] = fmaf(a[i], b[j], acc[i][j]);
        }
        __syncthreads();
    }

    float bv[8];
#pragma unroll
    for (int j = 0; j < 8; j++) bv[j] = bias[n0 + tx * 8 + j];

#pragma unroll
    for (int i = 0; i < 8; i++) {
        float* yp = Y + (size_t)(m0 + ty * 8 + i) * DMODEL + n0 + tx * 8;
        float4 v0, v1;
        v0.x = acc[i][0] + bv[0]; v0.y = acc[i][1] + bv[1];
        v0.z = acc[i][2] + bv[2]; v0.w = acc[i][3] + bv[3];
        v1.x = acc[i][4] + bv[4]; v1.y = acc[i][5] + bv[5];
        v1.z = acc[i][6] + bv[6]; v1.w = acc[i][7] + bv[7];
        *(float4*)(yp)     = v0;
        *(float4*)(yp + 4) = v1;
    }
}

// ---------------------------------------------------------------------------
// Flash attention: one CTA per (b, h, 64-row q tile). 256 threads.
// 64x64 S tile, 4x4 per thread with STRIDED (i*16) mapping -> conflict-free LDS.
// ---------------------------------------------------------------------------
__global__ __launch_bounds__(256)
void attn_kernel(const int* __restrict__ mask, float* __restrict__ out)
{
    extern __shared__ float sm[];
    float* Qs  = sm;                 // [64][65]
    float* Ks  = Qs + 64 * 65;       // [64][65]
    float* Ps  = Ks + 64 * 65;       // [64][65]
    float* Vs  = Ps + 64 * 65;       // [64][64]
    float* m_s = Vs + 64 * 64;       // [64]
    float* l_s = m_s + 64;           // [64]
    float* f_s = l_s + 64;           // [64]
    int*   msk = (int*)(f_s + 64);   // [64]

    const int tid = threadIdx.x;
    const int tx  = tid & 15;
    const int ty  = tid >> 4;
    const int q0  = blockIdx.x << 6;
    const int h   = blockIdx.y;
    const int b   = blockIdx.z;

    const float* qb = g_q + (size_t)b * SLEN * DMODEL + h * DHEAD;
    const float* kb = g_k + (size_t)b * SLEN * DMODEL + h * DHEAD;
    const float* vb = g_v + (size_t)b * SLEN * DMODEL + h * DHEAD;
    const int*   mb = mask + b * SLEN;

    // Load Q tile: Qs[r][d]
    for (int i = tid; i < 64 * 64; i += 256) {
        const int r = i >> 6, d = i & 63;
        Qs[r * 65 + d] = qb[(size_t)(q0 + r) * DMODEL + d];
    }
    if (tid < 64) { m_s[tid] = -1e30f; l_s[tid] = 0.f; }

    float O[4][4];
#pragma unroll
    for (int i = 0; i < 4; i++)
#pragma unroll
        for (int j = 0; j < 4; j++) O[i][j] = 0.f;

    __syncthreads();

    for (int k0 = 0; k0 < SLEN; k0 += 64) {
        // Load K, V tiles + mask slice
        for (int i = tid; i < 64 * 64; i += 256) {
            const int r = i >> 6, d = i & 63;
            const size_t g = (size_t)(k0 + r) * DMODEL + d;
            Ks[r * 65 + d] = kb[g];
            Vs[r * 64 + d] = vb[g];
        }
        if (tid < 64) msk[tid] = mb[k0 + tid];
        __syncthreads();

        // S = Q @ K^T  (rows ty+16i, cols tx+16j)
        float s[4][4];
#pragma unroll
        for (int i = 0; i < 4; i++)
#pragma unroll
            for (int j = 0; j < 4; j++) s[i][j] = 0.f;

#pragma unroll 8
        for (int d = 0; d < 64; d++) {
            float qv[4], kv[4];
#pragma unroll
            for (int i = 0; i < 4; i++) qv[i] = Qs[(ty + 16 * i) * 65 + d];
#pragma unroll
            for (int j = 0; j < 4; j++) kv[j] = Ks[(tx + 16 * j) * 65 + d];
#pragma unroll
            for (int i = 0; i < 4; i++)
#pragma unroll
                for (int j = 0; j < 4; j++)
                    s[i][j] = fmaf(qv[i], kv[j], s[i][j]);
        }

        // Scale + key-padding mask, write P tile
#pragma unroll
        for (int j = 0; j < 4; j++) {
            const int c = tx + 16 * j;
            const bool dead = (msk[c] == 0);
#pragma unroll
            for (int i = 0; i < 4; i++) {
                float v = s[i][j] * ATT_SCALE;
                if (dead) v = -1e9f;
                Ps[(ty + 16 * i) * 65 + c] = v;
            }
        }
        __syncthreads();

        // Online softmax: 4 threads per row, shfl reduce within group of 4
        {
            const int row = tid >> 2;
            const int seg = tid & 3;
            float* pr = Ps + row * 65 + seg * 16;
            float mx = -1e30f;
#pragma unroll
            for (int k2 = 0; k2 < 16; k2++) mx = fmaxf(mx, pr[k2]);
            mx = fmaxf(mx, __shfl_xor_sync(0xffffffffu, mx, 1));
            mx = fmaxf(mx, __shfl_xor_sync(0xffffffffu, mx, 2));
            const float mold = m_s[row];
            const float mnew = fmaxf(mold, mx);
            const float fac  = __expf(mold - mnew);
            float ssum = 0.f;
#pragma unroll
            for (int k2 = 0; k2 < 16; k2++) {
                const float p = __expf(pr[k2] - mnew);
                pr[k2] = p;
                ssum += p;
            }
            ssum += __shfl_xor_sync(0xffffffffu, ssum, 1);
            ssum += __shfl_xor_sync(0xffffffffu, ssum, 2);
            if (seg == 0) {
                m_s[row] = mnew;
                l_s[row] = fmaf(l_s[row], fac, ssum);
                f_s[row] = fac;
            }
        }
        __syncthreads();

        // Rescale O, then O += P @ V
        float fr[4];
#pragma unroll
        for (int i = 0; i < 4; i++) fr[i] = f_s[ty + 16 * i];
#pragma unroll
        for (int i = 0; i < 4; i++)
#pragma unroll
            for (int j = 0; j < 4; j++) O[i][j] *= fr[i];

#pragma unroll 8
        for (int c = 0; c < 64; c++) {
            float pv[4], vv[4];
#pragma unroll
            for (int i = 0; i < 4; i++) pv[i] = Ps[(ty + 16 * i) * 65 + c];
#pragma unroll
            for (int j = 0; j < 4; j++) vv[j] = Vs[c * 64 + tx + 16 * j];
#pragma unroll
            for (int i = 0; i < 4; i++)
#pragma unroll
                for (int j = 0; j < 4; j++)
                    O[i][j] = fmaf(pv[i], vv[j], O[i][j]);
        }
        __syncthreads();
    }

    // Epilogue: divide by l, write out[b, q, h*64 + dv]
    float linv[4];
#pragma unroll
    for (int i = 0; i < 4; i++) linv[i] = 1.f / l_s[ty + 16 * i];

#pragma unroll
    for (int i = 0; i < 4; i++) {
        float* op = out + ((size_t)b * SLEN + q0 + ty + 16 * i) * DMODEL + h * DHEAD;
#pragma unroll
        for (int j = 0; j < 4; j++)
            op[tx + 16 * j] = O[i][j] * linv[i];
    }
}

// ---------------------------------------------------------------------------
extern "C" void kernel_launch(void* const* d_in, const int* in_sizes, int n_in,
                              void* d_out, int out_size)
{
    const float* Q    = (const float*)d_in[0];
    const float* K    = (const float*)d_in[1];
    const float* V    = (const float*)d_in[2];
    const int*   mask = (const int*)d_in[3];
    const float* Wq   = (const float*)d_in[4];
    const float* bq   = (const float*)d_in[5];
    const float* Wk   = (const float*)d_in[6];
    const float* bk   = (const float*)d_in[7];
    const float* Wv   = (const float*)d_in[8];
    const float* bv   = (const float*)d_in[9];
    float* out = (float*)d_out;

    float *qd = nullptr, *kd = nullptr, *vd = nullptr;
    cudaGetSymbolAddress((void**)&qd, g_q);
    cudaGetSymbolAddress((void**)&kd, g_k);
    cudaGetSymbolAddress((void**)&vd, g_v);

    const dim3 pgrid(DMODEL / 128, (BATCH * SLEN) / 128);
    proj_kernel<<<pgrid, 256>>>(Q, Wq, bq, qd);
    proj_kernel<<<pgrid, 256>>>(K, Wk, bk, kd);
    proj_kernel<<<pgrid, 256>>>(V, Wv, bv, vd);

    const size_t smem = (size_t)(3 * 64 * 65 + 64 * 64 + 3 * 64) * sizeof(float)
                      + 64 * sizeof(int);
    cudaFuncSetAttribute(attn_kernel, cudaFuncAttributeMaxDynamicSharedMemorySize,
                         (int)smem);
    const dim3 agrid(SLEN / 64, NHEAD, BATCH);
    attn_kernel<<<agrid, 256, smem>>>(mask, out);
}

// round 3
// speedup vs baseline: 1.2890x; 1.2890x over previous
#include <cuda_runtime.h>
#include <math.h>
#include <stdint.h>

#define BATCH  4
#define SLEN   2048
#define DMODEL 1024
#define NHEAD  16
#define DHEAD  64
#define ATT_SCALE 0.125f   // 1/sqrt(64)

// ---------------------------------------------------------------------------
// Device scratch (no cudaMalloc allowed)
// ---------------------------------------------------------------------------
__device__ float g_q[BATCH * SLEN * DMODEL];
__device__ float g_k[BATCH * SLEN * DMODEL];
__device__ float g_v[BATCH * SLEN * DMODEL];

// ---------------------------------------------------------------------------
// Helpers
// ---------------------------------------------------------------------------
__device__ __forceinline__ float f2tf32(float x) {
    uint32_t u;
    asm("cvt.rna.tf32.f32 %0, %1;" : "=r"(u) : "f"(x));
    return __uint_as_float(u);
}

// m16n8k8 tf32 MMA (portable warp-level tensor op, valid on base sm_103)
__device__ __forceinline__ void mma8(float c[4], const uint32_t a[4],
                                     const uint32_t b[2]) {
    asm volatile(
        "mma.sync.aligned.m16n8k8.row.col.f32.tf32.tf32.f32 "
        "{%0,%1,%2,%3}, {%4,%5,%6,%7}, {%8,%9}, {%0,%1,%2,%3};"
        : "+f"(c[0]), "+f"(c[1]), "+f"(c[2]), "+f"(c[3])
        : "r"(a[0]), "r"(a[1]), "r"(a[2]), "r"(a[3]),
          "r"(b[0]), "r"(b[1]));
}

// ---------------------------------------------------------------------------
// Projection GEMM on tensor cores (3xTF32 split, fused in-kernel):
// Y[8192,1024] = X[8192,1024] @ W[1024,1024] + bias
// CTA tile 128x128, BK=32, 8 warps of 64x32. 256 threads.
// ---------------------------------------------------------------------------
#define PAD 36
#define PROJ_SMEM (4 * 128 * PAD * 4)   // 73728 bytes

__global__ __launch_bounds__(256, 2)
void proj_mma(const float* __restrict__ X, const float* __restrict__ W,
              const float* __restrict__ bias, float* __restrict__ Y)
{
    extern __shared__ float sm[];
    float* Ash = sm;                    // [128 m][PAD]  (tf32 hi)
    float* Asl = Ash + 128 * PAD;       // (residual lo)
    float* Bsh = Asl + 128 * PAD;       // [128 n][PAD]  W^T hi
    float* Bsl = Bsh + 128 * PAD;       // W^T lo

    const int tid  = threadIdx.x;
    const int lane = tid & 31;
    const int w    = tid >> 5;
    const int g    = lane >> 2;         // 0..7
    const int tig  = lane & 3;          // 0..3
    const int wm   = (w >> 2) * 64;     // warp m offset: 0 / 64
    const int wn   = (w & 3) * 32;      // warp n offset: 0/32/64/96
    const int m0   = blockIdx.y * 128;
    const int n0   = blockIdx.x * 128;

    float acc[4][4][4];
#pragma unroll
    for (int i = 0; i < 4; i++)
#pragma unroll
        for (int j = 0; j < 4; j++)
#pragma unroll
            for (int r = 0; r < 4; r++) acc[i][j][r] = 0.f;

    for (int k0 = 0; k0 < DMODEL; k0 += 32) {
        // ---- A tile: X[m0..m0+127][k0..k0+31], split hi/lo, row-major smem
#pragma unroll
        for (int it = 0; it < 4; it++) {
            const int idx = tid + it * 256;
            const int r = idx >> 3, c = (idx & 7) << 2;
            const float4 v = *(const float4*)(X + (size_t)(m0 + r) * DMODEL + k0 + c);
            float4 h, l;
            h.x = f2tf32(v.x); l.x = v.x - h.x;
            h.y = f2tf32(v.y); l.y = v.y - h.y;
            h.z = f2tf32(v.z); l.z = v.z - h.z;
            h.w = f2tf32(v.w); l.w = v.w - h.w;
            *(float4*)&Ash[r * PAD + c] = h;
            *(float4*)&Asl[r * PAD + c] = l;
        }
        // ---- B tile: W[k0..k0+31][n0..n0+127] transposed to [n][k] smem
#pragma unroll
        for (int it = 0; it < 4; it++) {
            const int idx = tid + it * 256;
            const int n  = idx & 127;
            const int k4 = (idx >> 7) << 2;
            float4 v;
            v.x = W[(size_t)(k0 + k4 + 0) * DMODEL + n0 + n];
            v.y = W[(size_t)(k0 + k4 + 1) * DMODEL + n0 + n];
            v.z = W[(size_t)(k0 + k4 + 2) * DMODEL + n0 + n];
            v.w = W[(size_t)(k0 + k4 + 3) * DMODEL + n0 + n];
            float4 h, l;
            h.x = f2tf32(v.x); l.x = v.x - h.x;
            h.y = f2tf32(v.y); l.y = v.y - h.y;
            h.z = f2tf32(v.z); l.z = v.z - h.z;
            h.w = f2tf32(v.w); l.w = v.w - h.w;
            *(float4*)&Bsh[n * PAD + k4] = h;
            *(float4*)&Bsl[n * PAD + k4] = l;
        }
        __syncthreads();

#pragma unroll
        for (int ks = 0; ks < 4; ks++) {
            const int kk = ks * 8;
            uint32_t bh[4][2], bl[4][2];
#pragma unroll
            for (int j = 0; j < 4; j++) {
                const int cb = (wn + j * 8 + g) * PAD + kk + tig;
                bh[j][0] = __float_as_uint(Bsh[cb]);
                bh[j][1] = __float_as_uint(Bsh[cb + 4]);
                bl[j][0] = __float_as_uint(Bsl[cb]);
                bl[j][1] = __float_as_uint(Bsl[cb + 4]);
            }
#pragma unroll
            for (int i = 0; i < 4; i++) {
                const int ra = (wm + i * 16 + g) * PAD + kk + tig;
                uint32_t ah[4], al[4];
                ah[0] = __float_as_uint(Ash[ra]);
                ah[1] = __float_as_uint(Ash[ra + 8 * PAD]);
                ah[2] = __float_as_uint(Ash[ra + 4]);
                ah[3] = __float_as_uint(Ash[ra + 8 * PAD + 4]);
                al[0] = __float_as_uint(Asl[ra]);
                al[1] = __float_as_uint(Asl[ra + 8 * PAD]);
                al[2] = __float_as_uint(Asl[ra + 4]);
                al[3] = __float_as_uint(Asl[ra + 8 * PAD + 4]);
#pragma unroll
                for (int j = 0; j < 4; j++) {
                    mma8(acc[i][j], ah, bh[j]);   // hh
                    mma8(acc[i][j], ah, bl[j]);   // hl
                    mma8(acc[i][j], al, bh[j]);   // lh
                }
            }
        }
        __syncthreads();
    }

    // ---- epilogue: + bias, float2 stores
#pragma unroll
    for (int j = 0; j < 4; j++) {
        const int col = n0 + wn + j * 8 + 2 * tig;
        const float bx = bias[col], by = bias[col + 1];
#pragma unroll
        for (int i = 0; i < 4; i++) {
            const int r0 = m0 + wm + i * 16 + g;
            float2 v0, v1;
            v0.x = acc[i][j][0] + bx; v0.y = acc[i][j][1] + by;
            v1.x = acc[i][j][2] + bx; v1.y = acc[i][j][3] + by;
            *(float2*)(Y + (size_t)r0 * DMODEL + col)       = v0;
            *(float2*)(Y + (size_t)(r0 + 8) * DMODEL + col) = v1;
        }
    }
}

// ---------------------------------------------------------------------------
// Flash attention (vectorized LDS): one CTA per (b, h, 64-row q tile).
// ---------------------------------------------------------------------------
#define APAD 68
__global__ __launch_bounds__(256, 3)
void attn_kernel(const int* __restrict__ mask, float* __restrict__ out)
{
    extern __shared__ float sm[];
    float* Qs  = sm;                 // [64][APAD]
    float* Ks  = Qs + 64 * APAD;
    float* Ps  = Ks + 64 * APAD;
    float* Vs  = Ps + 64 * APAD;     // Vs[key][dim]
    float* m_s = Vs + 64 * APAD;
    float* l_s = m_s + 64;
    float* f_s = l_s + 64;
    int*   msk = (int*)(f_s + 64);

    const int tid = threadIdx.x;
    const int tx  = tid & 15;
    const int ty  = tid >> 4;
    const int q0  = blockIdx.x << 6;
    const int h   = blockIdx.y;
    const int b   = blockIdx.z;

    const float* qb = g_q + (size_t)b * SLEN * DMODEL + h * DHEAD;
    const float* kb = g_k + (size_t)b * SLEN * DMODEL + h * DHEAD;
    const float* vb = g_v + (size_t)b * SLEN * DMODEL + h * DHEAD;
    const int*   mb = mask + b * SLEN;

    for (int i = tid; i < 1024; i += 256) {
        const int r = i >> 4, d = (i & 15) << 2;
        *(float4*)&Qs[r * APAD + d] =
            *(const float4*)(qb + (size_t)(q0 + r) * DMODEL + d);
    }
    if (tid < 64) { m_s[tid] = -1e30f; l_s[tid] = 0.f; }

    float O[4][4];
#pragma unroll
    for (int i = 0; i < 4; i++)
#pragma unroll
        for (int j = 0; j < 4; j++) O[i][j] = 0.f;

    __syncthreads();

    for (int k0 = 0; k0 < SLEN; k0 += 64) {
        for (int i = tid; i < 1024; i += 256) {
            const int r = i >> 4, d = (i & 15) << 2;
            const size_t gg = (size_t)(k0 + r) * DMODEL + d;
            *(float4*)&Ks[r * APAD + d] = *(const float4*)(kb + gg);
            *(float4*)&Vs[r * APAD + d] = *(const float4*)(vb + gg);
        }
        if (tid < 64) msk[tid] = mb[k0 + tid];
        __syncthreads();

        float s[4][4];
#pragma unroll
        for (int i = 0; i < 4; i++)
#pragma unroll
            for (int j = 0; j < 4; j++) s[i][j] = 0.f;

#pragma unroll 4
        for (int d = 0; d < 64; d += 4) {
            float4 q4[4], k4[4];
#pragma unroll
            for (int i = 0; i < 4; i++)
                q4[i] = *(const float4*)&Qs[(ty + 16 * i) * APAD + d];
#pragma unroll
            for (int j = 0; j < 4; j++)
                k4[j] = *(const float4*)&Ks[(tx + 16 * j) * APAD + d];
#pragma unroll
            for (int i = 0; i < 4; i++)
#pragma unroll
                for (int j = 0; j < 4; j++) {
                    s[i][j] = fmaf(q4[i].x, k4[j].x, s[i][j]);
                    s[i][j] = fmaf(q4[i].y, k4[j].y, s[i][j]);
                    s[i][j] = fmaf(q4[i].z, k4[j].z, s[i][j]);
                    s[i][j] = fmaf(q4[i].w, k4[j].w, s[i][j]);
                }
        }

#pragma unroll
        for (int j = 0; j < 4; j++) {
            const int c = tx + 16 * j;
            const bool dead = (msk[c] == 0);
#pragma unroll
            for (int i = 0; i < 4; i++) {
                float v = s[i][j] * ATT_SCALE;
                if (dead) v = -1e9f;
                Ps[(ty + 16 * i) * APAD + c] = v;
            }
        }
        __syncthreads();

        {
            const int row = tid >> 2;
            const int seg = tid & 3;
            float* pr = Ps + row * APAD + seg * 16;
            float4 p0 = ((float4*)pr)[0], p1 = ((float4*)pr)[1];
            float4 p2 = ((float4*)pr)[2], p3 = ((float4*)pr)[3];
            float mx = fmaxf(fmaxf(fmaxf(p0.x, p0.y), fmaxf(p0.z, p0.w)),
                      fmaxf(fmaxf(fmaxf(p1.x, p1.y), fmaxf(p1.z, p1.w)),
                      fmaxf(fmaxf(fmaxf(p2.x, p2.y), fmaxf(p2.z, p2.w)),
                            fmaxf(fmaxf(p3.x, p3.y), fmaxf(p3.z, p3.w)))));
            mx = fmaxf(mx, __shfl_xor_sync(0xffffffffu, mx, 1));
            mx = fmaxf(mx, __shfl_xor_sync(0xffffffffu, mx, 2));
            const float mold = m_s[row];
            const float mnew = fmaxf(mold, mx);
            const float fac  = __expf(mold - mnew);
            p0.x = __expf(p0.x - mnew); p0.y = __expf(p0.y - mnew);
            p0.z = __expf(p0.z - mnew); p0.w = __expf(p0.w - mnew);
            p1.x = __expf(p1.x - mnew); p1.y = __expf(p1.y - mnew);
            p1.z = __expf(p1.z - mnew); p1.w = __expf(p1.w - mnew);
            p2.x = __expf(p2.x - mnew); p2.y = __expf(p2.y - mnew);
            p2.z = __expf(p2.z - mnew); p2.w = __expf(p2.w - mnew);
            p3.x = __expf(p3.x - mnew); p3.y = __expf(p3.y - mnew);
            p3.z = __expf(p3.z - mnew); p3.w = __expf(p3.w - mnew);
            ((float4*)pr)[0] = p0; ((float4*)pr)[1] = p1;
            ((float4*)pr)[2] = p2; ((float4*)pr)[3] = p3;
            float ssum = (p0.x + p0.y + p0.z + p0.w) + (p1.x + p1.y + p1.z + p1.w)
                       + (p2.x + p2.y + p2.z + p2.w) + (p3.x + p3.y + p3.z + p3.w);
            ssum += __shfl_xor_sync(0xffffffffu, ssum, 1);
            ssum += __shfl_xor_sync(0xffffffffu, ssum, 2);
            if (seg == 0) {
                m_s[row] = mnew;
                l_s[row] = fmaf(l_s[row], fac, ssum);
                f_s[row] = fac;
            }
        }
        __syncthreads();

        float fr[4];
#pragma unroll
        for (int i = 0; i < 4; i++) fr[i] = f_s[ty + 16 * i];
#pragma unroll
        for (int i = 0; i < 4; i++)
#pragma unroll
            for (int j = 0; j < 4; j++) O[i][j] *= fr[i];

#pragma unroll 4
        for (int c = 0; c < 64; c += 4) {
            float4 p4[4];
#pragma unroll
            for (int i = 0; i < 4; i++)
                p4[i] = *(const float4*)&Ps[(ty + 16 * i) * APAD + c];
#pragma unroll
            for (int cc = 0; cc < 4; cc++) {
                float vv[4];
#pragma unroll
                for (int j = 0; j < 4; j++)
                    vv[j] = Vs[(c + cc) * APAD + tx + 16 * j];
#pragma unroll
                for (int i = 0; i < 4; i++) {
                    const float pv = ((const float*)&p4[i])[cc];
#pragma unroll
                    for (int j = 0; j < 4; j++)
                        O[i][j] = fmaf(pv, vv[j], O[i][j]);
                }
            }
        }
        __syncthreads();
    }

    float linv[4];
#pragma unroll
    for (int i = 0; i < 4; i++) linv[i] = 1.f / l_s[ty + 16 * i];

#pragma unroll
    for (int i = 0; i < 4; i++) {
        float* op = out + ((size_t)b * SLEN + q0 + ty + 16 * i) * DMODEL + h * DHEAD;
#pragma unroll
        for (int j = 0; j < 4; j++)
            op[tx + 16 * j] = O[i][j] * linv[i];
    }
}

// ---------------------------------------------------------------------------
extern "C" void kernel_launch(void* const* d_in, const int* in_sizes, int n_in,
                              void* d_out, int out_size)
{
    const float* Q    = (const float*)d_in[0];
    const float* K    = (const float*)d_in[1];
    const float* V    = (const float*)d_in[2];
    const int*   mask = (const int*)d_in[3];
    const float* Wq   = (const float*)d_in[4];
    const float* bq   = (const float*)d_in[5];
    const float* Wk   = (const float*)d_in[6];
    const float* bk   = (const float*)d_in[7];
    const float* Wv   = (const float*)d_in[8];
    const float* bv   = (const float*)d_in[9];
    float* out = (float*)d_out;

    float *qd, *kd, *vd;
    cudaGetSymbolAddress((void**)&qd, g_q);
    cudaGetSymbolAddress((void**)&kd, g_k);
    cudaGetSymbolAddress((void**)&vd, g_v);

    cudaFuncSetAttribute(proj_mma, cudaFuncAttributeMaxDynamicSharedMemorySize,
                         PROJ_SMEM);
    const dim3 pgrid(DMODEL / 128, (BATCH * SLEN) / 128);
    proj_mma<<<pgrid, 256, PROJ_SMEM>>>(Q, Wq, bq, qd);
    proj_mma<<<pgrid, 256, PROJ_SMEM>>>(K, Wk, bk, kd);
    proj_mma<<<pgrid, 256, PROJ_SMEM>>>(V, Wv, bv, vd);

    const size_t smem = (size_t)(4 * 64 * APAD + 3 * 64) * sizeof(float)
                      + 64 * sizeof(int);
    cudaFuncSetAttribute(attn_kernel, cudaFuncAttributeMaxDynamicSharedMemorySize,
                         (int)smem);
    const dim3 agrid(SLEN / 64, NHEAD, BATCH);
    attn_kernel<<<agrid, 256, smem>>>(mask, out);
}

// round 4
// speedup vs baseline: 1.6821x; 1.3049x over previous
#include <cuda_runtime.h>
#include <math.h>
#include <stdint.h>

#define BATCH  4
#define SLEN   2048
#define DMODEL 1024
#define NHEAD  16
#define DHEAD  64
#define ATT_SCALE 0.125f   // 1/sqrt(64)

// ---------------------------------------------------------------------------
// Device scratch (no cudaMalloc allowed)
// ---------------------------------------------------------------------------
__device__ float g_q[BATCH * SLEN * DMODEL];
__device__ float g_k[BATCH * SLEN * DMODEL];
__device__ float g_v[BATCH * SLEN * DMODEL];

// ---------------------------------------------------------------------------
// Helpers
// ---------------------------------------------------------------------------
__device__ __forceinline__ float f2tf32(float x) {
    uint32_t u;
    asm("cvt.rna.tf32.f32 %0, %1;" : "=r"(u) : "f"(x));
    return __uint_as_float(u);
}

// m16n8k8 tf32 MMA (portable warp-level tensor op, valid on base sm_103)
__device__ __forceinline__ void mma8(float c[4], const uint32_t a[4],
                                     const uint32_t b[2]) {
    asm volatile(
        "mma.sync.aligned.m16n8k8.row.col.f32.tf32.tf32.f32 "
        "{%0,%1,%2,%3}, {%4,%5,%6,%7}, {%8,%9}, {%0,%1,%2,%3};"
        : "+f"(c[0]), "+f"(c[1]), "+f"(c[2]), "+f"(c[3])
        : "r"(a[0]), "r"(a[1]), "r"(a[2]), "r"(a[3]),
          "r"(b[0]), "r"(b[1]));
}

__device__ __forceinline__ void split4(const float v[4], uint32_t h[4],
                                       uint32_t l[4]) {
#pragma unroll
    for (int i = 0; i < 4; i++) {
        const float hv = f2tf32(v[i]);
        h[i] = __float_as_uint(hv);
        l[i] = __float_as_uint(v[i] - hv);
    }
}

// ---------------------------------------------------------------------------
// Projection GEMM on tensor cores (3xTF32 split, fused in-kernel):
// Y[8192,1024] = X[8192,1024] @ W[1024,1024] + bias
// CTA tile 128x128, BK=32, 8 warps of 64x32. 256 threads.
// ---------------------------------------------------------------------------
#define PAD 36
#define PROJ_SMEM (4 * 128 * PAD * 4)   // 73728 bytes

__global__ __launch_bounds__(256, 2)
void proj_mma(const float* __restrict__ X, const float* __restrict__ W,
              const float* __restrict__ bias, float* __restrict__ Y)
{
    extern __shared__ float sm[];
    float* Ash = sm;                    // [128 m][PAD]  (tf32 hi)
    float* Asl = Ash + 128 * PAD;       // (residual lo)
    float* Bsh = Asl + 128 * PAD;       // [128 n][PAD]  W^T hi
    float* Bsl = Bsh + 128 * PAD;       // W^T lo

    const int tid  = threadIdx.x;
    const int lane = tid & 31;
    const int w    = tid >> 5;
    const int g    = lane >> 2;         // 0..7
    const int tig  = lane & 3;          // 0..3
    const int wm   = (w >> 2) * 64;
    const int wn   = (w & 3) * 32;
    const int m0   = blockIdx.y * 128;
    const int n0   = blockIdx.x * 128;

    float acc[4][4][4];
#pragma unroll
    for (int i = 0; i < 4; i++)
#pragma unroll
        for (int j = 0; j < 4; j++)
#pragma unroll
            for (int r = 0; r < 4; r++) acc[i][j][r] = 0.f;

    for (int k0 = 0; k0 < DMODEL; k0 += 32) {
#pragma unroll
        for (int it = 0; it < 4; it++) {
            const int idx = tid + it * 256;
            const int r = idx >> 3, c = (idx & 7) << 2;
            const float4 v = *(const float4*)(X + (size_t)(m0 + r) * DMODEL + k0 + c);
            float4 h, l;
            h.x = f2tf32(v.x); l.x = v.x - h.x;
            h.y = f2tf32(v.y); l.y = v.y - h.y;
            h.z = f2tf32(v.z); l.z = v.z - h.z;
            h.w = f2tf32(v.w); l.w = v.w - h.w;
            *(float4*)&Ash[r * PAD + c] = h;
            *(float4*)&Asl[r * PAD + c] = l;
        }
#pragma unroll
        for (int it = 0; it < 4; it++) {
            const int idx = tid + it * 256;
            const int n  = idx & 127;
            const int k4 = (idx >> 7) << 2;
            float4 v;
            v.x = W[(size_t)(k0 + k4 + 0) * DMODEL + n0 + n];
            v.y = W[(size_t)(k0 + k4 + 1) * DMODEL + n0 + n];
            v.z = W[(size_t)(k0 + k4 + 2) * DMODEL + n0 + n];
            v.w = W[(size_t)(k0 + k4 + 3) * DMODEL + n0 + n];
            float4 h, l;
            h.x = f2tf32(v.x); l.x = v.x - h.x;
            h.y = f2tf32(v.y); l.y = v.y - h.y;
            h.z = f2tf32(v.z); l.z = v.z - h.z;
            h.w = f2tf32(v.w); l.w = v.w - h.w;
            *(float4*)&Bsh[n * PAD + k4] = h;
            *(float4*)&Bsl[n * PAD + k4] = l;
        }
        __syncthreads();

#pragma unroll
        for (int ks = 0; ks < 4; ks++) {
            const int kk = ks * 8;
            uint32_t bh[4][2], bl[4][2];
#pragma unroll
            for (int j = 0; j < 4; j++) {
                const int cb = (wn + j * 8 + g) * PAD + kk + tig;
                bh[j][0] = __float_as_uint(Bsh[cb]);
                bh[j][1] = __float_as_uint(Bsh[cb + 4]);
                bl[j][0] = __float_as_uint(Bsl[cb]);
                bl[j][1] = __float_as_uint(Bsl[cb + 4]);
            }
#pragma unroll
            for (int i = 0; i < 4; i++) {
                const int ra = (wm + i * 16 + g) * PAD + kk + tig;
                uint32_t ah[4], al[4];
                ah[0] = __float_as_uint(Ash[ra]);
                ah[1] = __float_as_uint(Ash[ra + 8 * PAD]);
                ah[2] = __float_as_uint(Ash[ra + 4]);
                ah[3] = __float_as_uint(Ash[ra + 8 * PAD + 4]);
                al[0] = __float_as_uint(Asl[ra]);
                al[1] = __float_as_uint(Asl[ra + 8 * PAD]);
                al[2] = __float_as_uint(Asl[ra + 4]);
                al[3] = __float_as_uint(Asl[ra + 8 * PAD + 4]);
#pragma unroll
                for (int j = 0; j < 4; j++) {
                    mma8(acc[i][j], ah, bh[j]);
                    mma8(acc[i][j], ah, bl[j]);
                    mma8(acc[i][j], al, bh[j]);
                }
            }
        }
        __syncthreads();
    }

#pragma unroll
    for (int j = 0; j < 4; j++) {
        const int col = n0 + wn + j * 8 + 2 * tig;
        const float bx = bias[col], by = bias[col + 1];
#pragma unroll
        for (int i = 0; i < 4; i++) {
            const int r0 = m0 + wm + i * 16 + g;
            float2 v0, v1;
            v0.x = acc[i][j][0] + bx; v0.y = acc[i][j][1] + by;
            v1.x = acc[i][j][2] + bx; v1.y = acc[i][j][3] + by;
            *(float2*)(Y + (size_t)r0 * DMODEL + col)       = v0;
            *(float2*)(Y + (size_t)(r0 + 8) * DMODEL + col) = v1;
        }
    }
}

// ---------------------------------------------------------------------------
// Flash attention on tensor cores (3xTF32 split both GEMMs).
// CTA: 256 threads / 8 warps. Q tile = 128 rows (warp = 16), key tile = 64.
// ---------------------------------------------------------------------------
#define QPAD 68
#define KPAD 68
#define VPAD 72
#define PPAD 68
#define ATTN_SMEM ((128 * QPAD + 64 * KPAD + 64 * VPAD + 128 * PPAD + 64) * 4)

__global__ __launch_bounds__(256, 2)
void attn_mma(const int* __restrict__ mask, float* __restrict__ out)
{
    extern __shared__ float sm[];
    float* Qs  = sm;                      // [128][QPAD] fp32
    float* Ks  = Qs + 128 * QPAD;         // [64][KPAD]
    float* Vs  = Ks + 64 * KPAD;          // [64][VPAD]
    float* Ps  = Vs + 64 * VPAD;          // [128][PPAD]
    int*   msk = (int*)(Ps + 128 * PPAD); // [64]

    const int tid  = threadIdx.x;
    const int lane = tid & 31;
    const int w    = tid >> 5;
    const int g    = lane >> 2;
    const int tig  = lane & 3;
    const int wm   = w * 16;
    const int q0   = blockIdx.x << 7;
    const int h    = blockIdx.y;
    const int b    = blockIdx.z;

    const float* qb = g_q + (size_t)b * SLEN * DMODEL + h * DHEAD;
    const float* kb = g_k + (size_t)b * SLEN * DMODEL + h * DHEAD;
    const float* vb = g_v + (size_t)b * SLEN * DMODEL + h * DHEAD;
    const int*   mb = mask + b * SLEN;

    // Load Q tile (fp32, float4)
    for (int i = tid; i < 2048; i += 256) {
        const int r = i >> 4, d = (i & 15) << 2;
        *(float4*)&Qs[r * QPAD + d] =
            *(const float4*)(qb + (size_t)(q0 + r) * DMODEL + d);
    }

    float O[8][4];
#pragma unroll
    for (int j = 0; j < 8; j++)
#pragma unroll
        for (int r = 0; r < 4; r++) O[j][r] = 0.f;
    float mrow0 = -1e30f, mrow1 = -1e30f, lrow0 = 0.f, lrow1 = 0.f;

    __syncthreads();

    for (int k0 = 0; k0 < SLEN; k0 += 64) {
        // ---- fill K, V (fp32) + mask slice
        for (int i = tid; i < 1024; i += 256) {
            const int r = i >> 4, d = (i & 15) << 2;
            const size_t gg = (size_t)(k0 + r) * DMODEL + d;
            *(float4*)&Ks[r * KPAD + d] = *(const float4*)(kb + gg);
            *(float4*)&Vs[r * VPAD + d] = *(const float4*)(vb + gg);
        }
        if (tid < 64) msk[tid] = mb[k0 + tid];
        __syncthreads();

        // ---- S = Q @ K^T (3xTF32)
        float S[8][4];
#pragma unroll
        for (int j = 0; j < 8; j++)
#pragma unroll
            for (int r = 0; r < 4; r++) S[j][r] = 0.f;

#pragma unroll
        for (int ks = 0; ks < 8; ks++) {
            const int kk = ks * 8;
            float av[4];
            av[0] = Qs[(wm + g) * QPAD + kk + tig];
            av[1] = Qs[(wm + g + 8) * QPAD + kk + tig];
            av[2] = Qs[(wm + g) * QPAD + kk + tig + 4];
            av[3] = Qs[(wm + g + 8) * QPAD + kk + tig + 4];
            uint32_t ah[4], al[4];
            split4(av, ah, al);
#pragma unroll
            for (int j = 0; j < 8; j++) {
                const int cb = (j * 8 + g) * KPAD + kk + tig;
                const float b0 = Ks[cb], b1 = Ks[cb + 4];
                const float h0 = f2tf32(b0), h1 = f2tf32(b1);
                uint32_t bh[2] = { __float_as_uint(h0), __float_as_uint(h1) };
                uint32_t bl[2] = { __float_as_uint(b0 - h0),
                                   __float_as_uint(b1 - h1) };
                mma8(S[j], ah, bh);
                mma8(S[j], ah, bl);
                mma8(S[j], al, bh);
            }
        }

        // ---- scale + mask (in registers)
        float mx0 = -1e30f, mx1 = -1e30f;
#pragma unroll
        for (int j = 0; j < 8; j++) {
            const int c = j * 8 + 2 * tig;
            const bool d0 = (msk[c] == 0);
            const bool d1 = (msk[c + 1] == 0);
            S[j][0] = d0 ? -1e9f : S[j][0] * ATT_SCALE;
            S[j][1] = d1 ? -1e9f : S[j][1] * ATT_SCALE;
            S[j][2] = d0 ? -1e9f : S[j][2] * ATT_SCALE;
            S[j][3] = d1 ? -1e9f : S[j][3] * ATT_SCALE;
            mx0 = fmaxf(mx0, fmaxf(S[j][0], S[j][1]));
            mx1 = fmaxf(mx1, fmaxf(S[j][2], S[j][3]));
        }
        // quad reduce over tig (lanes g*4+tig)
        mx0 = fmaxf(mx0, __shfl_xor_sync(0xffffffffu, mx0, 1));
        mx0 = fmaxf(mx0, __shfl_xor_sync(0xffffffffu, mx0, 2));
        mx1 = fmaxf(mx1, __shfl_xor_sync(0xffffffffu, mx1, 1));
        mx1 = fmaxf(mx1, __shfl_xor_sync(0xffffffffu, mx1, 2));

        const float mnew0 = fmaxf(mrow0, mx0);
        const float mnew1 = fmaxf(mrow1, mx1);
        const float fac0  = __expf(mrow0 - mnew0);
        const float fac1  = __expf(mrow1 - mnew1);

        // ---- exp, write P (fp32) to smem, accumulate row sums
        float sum0 = 0.f, sum1 = 0.f;
#pragma unroll
        for (int j = 0; j < 8; j++) {
            const int c = j * 8 + 2 * tig;
            const float p0 = __expf(S[j][0] - mnew0);
            const float p1 = __expf(S[j][1] - mnew0);
            const float p2 = __expf(S[j][2] - mnew1);
            const float p3 = __expf(S[j][3] - mnew1);
            sum0 += p0 + p1;
            sum1 += p2 + p3;
            float2 t0, t1;
            t0.x = p0; t0.y = p1;
            t1.x = p2; t1.y = p3;
            *(float2*)&Ps[(wm + g) * PPAD + c]     = t0;
            *(float2*)&Ps[(wm + g + 8) * PPAD + c] = t1;
        }
        sum0 += __shfl_xor_sync(0xffffffffu, sum0, 1);
        sum0 += __shfl_xor_sync(0xffffffffu, sum0, 2);
        sum1 += __shfl_xor_sync(0xffffffffu, sum1, 1);
        sum1 += __shfl_xor_sync(0xffffffffu, sum1, 2);

        lrow0 = lrow0 * fac0 + sum0;
        lrow1 = lrow1 * fac1 + sum1;
        mrow0 = mnew0;
        mrow1 = mnew1;

        // rescale O
#pragma unroll
        for (int j = 0; j < 8; j++) {
            O[j][0] *= fac0; O[j][1] *= fac0;
            O[j][2] *= fac1; O[j][3] *= fac1;
        }
        __syncwarp();   // P rows are warp-private; no block sync needed

        // ---- O += P @ V (3xTF32)
#pragma unroll
        for (int ks = 0; ks < 8; ks++) {
            const int kk = ks * 8;
            float av[4];
            av[0] = Ps[(wm + g) * PPAD + kk + tig];
            av[1] = Ps[(wm + g + 8) * PPAD + kk + tig];
            av[2] = Ps[(wm + g) * PPAD + kk + tig + 4];
            av[3] = Ps[(wm + g + 8) * PPAD + kk + tig + 4];
            uint32_t ah[4], al[4];
            split4(av, ah, al);
#pragma unroll
            for (int jn = 0; jn < 8; jn++) {
                const float b0 = Vs[(kk + tig) * VPAD + jn * 8 + g];
                const float b1 = Vs[(kk + tig + 4) * VPAD + jn * 8 + g];
                const float h0 = f2tf32(b0), h1 = f2tf32(b1);
                uint32_t bh[2] = { __float_as_uint(h0), __float_as_uint(h1) };
                uint32_t bl[2] = { __float_as_uint(b0 - h0),
                                   __float_as_uint(b1 - h1) };
                mma8(O[jn], ah, bh);
                mma8(O[jn], ah, bl);
                mma8(O[jn], al, bh);
            }
        }
        __syncthreads();   // before next tile overwrites Ks/Vs
    }

    // ---- epilogue: normalize + store (float2)
    const float inv0 = 1.f / lrow0;
    const float inv1 = 1.f / lrow1;
    const int row0 = q0 + wm + g;
#pragma unroll
    for (int jn = 0; jn < 8; jn++) {
        const int col = h * DHEAD + jn * 8 + 2 * tig;
        float2 v0, v1;
        v0.x = O[jn][0] * inv0; v0.y = O[jn][1] * inv0;
        v1.x = O[jn][2] * inv1; v1.y = O[jn][3] * inv1;
        *(float2*)(out + ((size_t)b * SLEN + row0) * DMODEL + col)     = v0;
        *(float2*)(out + ((size_t)b * SLEN + row0 + 8) * DMODEL + col) = v1;
    }
}

// ---------------------------------------------------------------------------
extern "C" void kernel_launch(void* const* d_in, const int* in_sizes, int n_in,
                              void* d_out, int out_size)
{
    const float* Q    = (const float*)d_in[0];
    const float* K    = (const float*)d_in[1];
    const float* V    = (const float*)d_in[2];
    const int*   mask = (const int*)d_in[3];
    const float* Wq   = (const float*)d_in[4];
    const float* bq   = (const float*)d_in[5];
    const float* Wk   = (const float*)d_in[6];
    const float* bk   = (const float*)d_in[7];
    const float* Wv   = (const float*)d_in[8];
    const float* bv   = (const float*)d_in[9];
    float* out = (float*)d_out;

    float *qd, *kd, *vd;
    cudaGetSymbolAddress((void**)&qd, g_q);
    cudaGetSymbolAddress((void**)&kd, g_k);
    cudaGetSymbolAddress((void**)&vd, g_v);

    cudaFuncSetAttribute(proj_mma, cudaFuncAttributeMaxDynamicSharedMemorySize,
                         PROJ_SMEM);
    const dim3 pgrid(DMODEL / 128, (BATCH * SLEN) / 128);
    proj_mma<<<pgrid, 256, PROJ_SMEM>>>(Q, Wq, bq, qd);
    proj_mma<<<pgrid, 256, PROJ_SMEM>>>(K, Wk, bk, kd);
    proj_mma<<<pgrid, 256, PROJ_SMEM>>>(V, Wv, bv, vd);

    cudaFuncSetAttribute(attn_mma, cudaFuncAttributeMaxDynamicSharedMemorySize,
                         ATTN_SMEM);
    const dim3 agrid(SLEN / 128, NHEAD, BATCH);
    attn_mma<<<agrid, 256, ATTN_SMEM>>>(mask, out);
}

// round 5
// speedup vs baseline: 1.9096x; 1.1353x over previous
#include <cuda_runtime.h>
#include <math.h>
#include <stdint.h>

#define BATCH  4
#define SLEN   2048
#define DMODEL 1024
#define NHEAD  16
#define DHEAD  64
#define ATT_SCALE 0.125f   // 1/sqrt(64)

// ---------------------------------------------------------------------------
// Device scratch (no cudaMalloc allowed)
// ---------------------------------------------------------------------------
__device__ float g_q[BATCH * SLEN * DMODEL];
__device__ float g_k[BATCH * SLEN * DMODEL];
__device__ float g_v[BATCH * SLEN * DMODEL];

// ---------------------------------------------------------------------------
// Helpers
// ---------------------------------------------------------------------------
__device__ __forceinline__ float f2tf32(float x) {
    uint32_t u;
    asm("cvt.rna.tf32.f32 %0, %1;" : "=r"(u) : "f"(x));
    return __uint_as_float(u);
}

// m16n8k8 tf32 MMA (portable warp-level tensor op, valid on base sm_103)
__device__ __forceinline__ void mma8(float c[4], const uint32_t a[4],
                                     const uint32_t b[2]) {
    asm volatile(
        "mma.sync.aligned.m16n8k8.row.col.f32.tf32.tf32.f32 "
        "{%0,%1,%2,%3}, {%4,%5,%6,%7}, {%8,%9}, {%0,%1,%2,%3};"
        : "+f"(c[0]), "+f"(c[1]), "+f"(c[2]), "+f"(c[3])
        : "r"(a[0]), "r"(a[1]), "r"(a[2]), "r"(a[3]),
          "r"(b[0]), "r"(b[1]));
}

__device__ __forceinline__ void split4(const float v[4], uint32_t h[4],
                                       uint32_t l[4]) {
#pragma unroll
    for (int i = 0; i < 4; i++) {
        const float hv = f2tf32(v[i]);
        h[i] = __float_as_uint(hv);
        l[i] = __float_as_uint(v[i] - hv);
    }
}

// ---------------------------------------------------------------------------
// Fused projection GEMMs (Q, K, V in one launch; blockIdx.z selects).
// Y[8192,1024] = X @ W + bias, 3xTF32 split, CTA tile 128x128, BK=32.
// ---------------------------------------------------------------------------
#define PAD 36
#define PROJ_SMEM (4 * 128 * PAD * 4)   // 73728 bytes

__global__ __launch_bounds__(256, 2)
void proj_mma(const float* __restrict__ X0, const float* __restrict__ X1,
              const float* __restrict__ X2,
              const float* __restrict__ W0, const float* __restrict__ W1,
              const float* __restrict__ W2,
              const float* __restrict__ b0, const float* __restrict__ b1,
              const float* __restrict__ b2,
              float* __restrict__ Y0, float* __restrict__ Y1,
              float* __restrict__ Y2)
{
    extern __shared__ float sm[];
    float* Ash = sm;
    float* Asl = Ash + 128 * PAD;
    float* Bsh = Asl + 128 * PAD;
    float* Bsl = Bsh + 128 * PAD;

    const int z = blockIdx.z;
    const float* X    = (z == 0) ? X0 : (z == 1) ? X1 : X2;
    const float* W    = (z == 0) ? W0 : (z == 1) ? W1 : W2;
    const float* bias = (z == 0) ? b0 : (z == 1) ? b1 : b2;
    float*       Y    = (z == 0) ? Y0 : (z == 1) ? Y1 : Y2;

    const int tid  = threadIdx.x;
    const int lane = tid & 31;
    const int w    = tid >> 5;
    const int g    = lane >> 2;
    const int tig  = lane & 3;
    const int wm   = (w >> 2) * 64;
    const int wn   = (w & 3) * 32;
    const int m0   = blockIdx.y * 128;
    const int n0   = blockIdx.x * 128;

    float acc[4][4][4];
#pragma unroll
    for (int i = 0; i < 4; i++)
#pragma unroll
        for (int j = 0; j < 4; j++)
#pragma unroll
            for (int r = 0; r < 4; r++) acc[i][j][r] = 0.f;

    for (int k0 = 0; k0 < DMODEL; k0 += 32) {
#pragma unroll
        for (int it = 0; it < 4; it++) {
            const int idx = tid + it * 256;
            const int r = idx >> 3, c = (idx & 7) << 2;
            const float4 v = *(const float4*)(X + (size_t)(m0 + r) * DMODEL + k0 + c);
            float4 h, l;
            h.x = f2tf32(v.x); l.x = v.x - h.x;
            h.y = f2tf32(v.y); l.y = v.y - h.y;
            h.z = f2tf32(v.z); l.z = v.z - h.z;
            h.w = f2tf32(v.w); l.w = v.w - h.w;
            *(float4*)&Ash[r * PAD + c] = h;
            *(float4*)&Asl[r * PAD + c] = l;
        }
#pragma unroll
        for (int it = 0; it < 4; it++) {
            const int idx = tid + it * 256;
            const int n  = idx & 127;
            const int k4 = (idx >> 7) << 2;
            float4 v;
            v.x = W[(size_t)(k0 + k4 + 0) * DMODEL + n0 + n];
            v.y = W[(size_t)(k0 + k4 + 1) * DMODEL + n0 + n];
            v.z = W[(size_t)(k0 + k4 + 2) * DMODEL + n0 + n];
            v.w = W[(size_t)(k0 + k4 + 3) * DMODEL + n0 + n];
            float4 h, l;
            h.x = f2tf32(v.x); l.x = v.x - h.x;
            h.y = f2tf32(v.y); l.y = v.y - h.y;
            h.z = f2tf32(v.z); l.z = v.z - h.z;
            h.w = f2tf32(v.w); l.w = v.w - h.w;
            *(float4*)&Bsh[n * PAD + k4] = h;
            *(float4*)&Bsl[n * PAD + k4] = l;
        }
        __syncthreads();

#pragma unroll
        for (int ks = 0; ks < 4; ks++) {
            const int kk = ks * 8;
            uint32_t bh[4][2], bl[4][2];
#pragma unroll
            for (int j = 0; j < 4; j++) {
                const int cb = (wn + j * 8 + g) * PAD + kk + tig;
                bh[j][0] = __float_as_uint(Bsh[cb]);
                bh[j][1] = __float_as_uint(Bsh[cb + 4]);
                bl[j][0] = __float_as_uint(Bsl[cb]);
                bl[j][1] = __float_as_uint(Bsl[cb + 4]);
            }
#pragma unroll
            for (int i = 0; i < 4; i++) {
                const int ra = (wm + i * 16 + g) * PAD + kk + tig;
                uint32_t ah[4], al[4];
                ah[0] = __float_as_uint(Ash[ra]);
                ah[1] = __float_as_uint(Ash[ra + 8 * PAD]);
                ah[2] = __float_as_uint(Ash[ra + 4]);
                ah[3] = __float_as_uint(Ash[ra + 8 * PAD + 4]);
                al[0] = __float_as_uint(Asl[ra]);
                al[1] = __float_as_uint(Asl[ra + 8 * PAD]);
                al[2] = __float_as_uint(Asl[ra + 4]);
                al[3] = __float_as_uint(Asl[ra + 8 * PAD + 4]);
#pragma unroll
                for (int j = 0; j < 4; j++) {
                    mma8(acc[i][j], ah, bh[j]);
                    mma8(acc[i][j], ah, bl[j]);
                    mma8(acc[i][j], al, bh[j]);
                }
            }
        }
        __syncthreads();
    }

#pragma unroll
    for (int j = 0; j < 4; j++) {
        const int col = n0 + wn + j * 8 + 2 * tig;
        const float bx = bias[col], by = bias[col + 1];
#pragma unroll
        for (int i = 0; i < 4; i++) {
            const int r0 = m0 + wm + i * 16 + g;
            float2 v0, v1;
            v0.x = acc[i][j][0] + bx; v0.y = acc[i][j][1] + by;
            v1.x = acc[i][j][2] + bx; v1.y = acc[i][j][3] + by;
            *(float2*)(Y + (size_t)r0 * DMODEL + col)       = v0;
            *(float2*)(Y + (size_t)(r0 + 8) * DMODEL + col) = v1;
        }
    }
}

// ---------------------------------------------------------------------------
// Flash attention, tensor cores, pre-split K/V, register-shuffled P.
// CTA: 256 threads / 8 warps. Q tile = 128 rows (warp = 16), key tile = 64.
// ---------------------------------------------------------------------------
#define QPAD 68
#define KPAD 68
#define VPAD 72
#define ATTN_SMEM ((128 * QPAD + 2 * 64 * KPAD + 2 * 64 * VPAD) * 4 + 64 * 4)

__global__ __launch_bounds__(256, 2)
void attn_mma(const int* __restrict__ mask, float* __restrict__ out)
{
    extern __shared__ float sm[];
    float* Qs  = sm;                       // [128][QPAD] fp32
    float* Khi = Qs + 128 * QPAD;          // [64][KPAD] tf32 hi
    float* Klo = Khi + 64 * KPAD;          // residual lo
    float* Vhi = Klo + 64 * KPAD;          // [64][VPAD]
    float* Vlo = Vhi + 64 * VPAD;
    int*   msk = (int*)(Vlo + 64 * VPAD);  // [64]

    const int tid  = threadIdx.x;
    const int lane = tid & 31;
    const int w    = tid >> 5;
    const int g    = lane >> 2;
    const int tig  = lane & 3;
    const int wm   = w * 16;
    const int q0   = blockIdx.x << 7;
    const int h    = blockIdx.y;
    const int b    = blockIdx.z;

    const float* qb = g_q + (size_t)b * SLEN * DMODEL + h * DHEAD;
    const float* kb = g_k + (size_t)b * SLEN * DMODEL + h * DHEAD;
    const float* vb = g_v + (size_t)b * SLEN * DMODEL + h * DHEAD;
    const int*   mb = mask + b * SLEN;

    for (int i = tid; i < 2048; i += 256) {
        const int r = i >> 4, d = (i & 15) << 2;
        *(float4*)&Qs[r * QPAD + d] =
            *(const float4*)(qb + (size_t)(q0 + r) * DMODEL + d);
    }

    float O[8][4];
#pragma unroll
    for (int j = 0; j < 8; j++)
#pragma unroll
        for (int r = 0; r < 4; r++) O[j][r] = 0.f;
    float mrow0 = -1e30f, mrow1 = -1e30f, lrow0 = 0.f, lrow1 = 0.f;

    const unsigned FULL = 0xffffffffu;
    const int sbase = lane & 28;          // 4*g
    const int s0 = sbase + (tig >> 1);
    const int s1 = s0 + 2;
    const bool odd = (tig & 1) != 0;

    __syncthreads();

    for (int k0 = 0; k0 < SLEN; k0 += 64) {
        // ---- fill K, V tiles pre-split into tf32 hi + fp32 residual
        for (int i = tid; i < 1024; i += 256) {
            const int r = i >> 4, d = (i & 15) << 2;
            const size_t gg = (size_t)(k0 + r) * DMODEL + d;
            const float4 kv = *(const float4*)(kb + gg);
            const float4 vv = *(const float4*)(vb + gg);
            float4 h4, l4;
            h4.x = f2tf32(kv.x); l4.x = kv.x - h4.x;
            h4.y = f2tf32(kv.y); l4.y = kv.y - h4.y;
            h4.z = f2tf32(kv.z); l4.z = kv.z - h4.z;
            h4.w = f2tf32(kv.w); l4.w = kv.w - h4.w;
            *(float4*)&Khi[r * KPAD + d] = h4;
            *(float4*)&Klo[r * KPAD + d] = l4;
            h4.x = f2tf32(vv.x); l4.x = vv.x - h4.x;
            h4.y = f2tf32(vv.y); l4.y = vv.y - h4.y;
            h4.z = f2tf32(vv.z); l4.z = vv.z - h4.z;
            h4.w = f2tf32(vv.w); l4.w = vv.w - h4.w;
            *(float4*)&Vhi[r * VPAD + d] = h4;
            *(float4*)&Vlo[r * VPAD + d] = l4;
        }
        if (tid < 64) msk[tid] = mb[k0 + tid];
        __syncthreads();

        // ---- S = Q @ K^T (3xTF32; K pre-split, Q split on the fly)
        float S[8][4];
#pragma unroll
        for (int j = 0; j < 8; j++)
#pragma unroll
            for (int r = 0; r < 4; r++) S[j][r] = 0.f;

#pragma unroll
        for (int ks = 0; ks < 8; ks++) {
            const int kk = ks * 8;
            float av[4];
            av[0] = Qs[(wm + g) * QPAD + kk + tig];
            av[1] = Qs[(wm + g + 8) * QPAD + kk + tig];
            av[2] = Qs[(wm + g) * QPAD + kk + tig + 4];
            av[3] = Qs[(wm + g + 8) * QPAD + kk + tig + 4];
            uint32_t ah[4], al[4];
            split4(av, ah, al);
#pragma unroll
            for (int j = 0; j < 8; j++) {
                const int cb = (j * 8 + g) * KPAD + kk + tig;
                uint32_t bh[2] = { __float_as_uint(Khi[cb]),
                                   __float_as_uint(Khi[cb + 4]) };
                uint32_t bl[2] = { __float_as_uint(Klo[cb]),
                                   __float_as_uint(Klo[cb + 4]) };
                mma8(S[j], ah, bh);
                mma8(S[j], ah, bl);
                mma8(S[j], al, bh);
            }
        }

        // ---- scale + mask (registers)
        float mx0 = -1e30f, mx1 = -1e30f;
#pragma unroll
        for (int j = 0; j < 8; j++) {
            const int c = j * 8 + 2 * tig;
            const bool d0 = (msk[c] == 0);
            const bool d1 = (msk[c + 1] == 0);
            S[j][0] = d0 ? -1e9f : S[j][0] * ATT_SCALE;
            S[j][1] = d1 ? -1e9f : S[j][1] * ATT_SCALE;
            S[j][2] = d0 ? -1e9f : S[j][2] * ATT_SCALE;
            S[j][3] = d1 ? -1e9f : S[j][3] * ATT_SCALE;
            mx0 = fmaxf(mx0, fmaxf(S[j][0], S[j][1]));
            mx1 = fmaxf(mx1, fmaxf(S[j][2], S[j][3]));
        }
        mx0 = fmaxf(mx0, __shfl_xor_sync(FULL, mx0, 1));
        mx0 = fmaxf(mx0, __shfl_xor_sync(FULL, mx0, 2));
        mx1 = fmaxf(mx1, __shfl_xor_sync(FULL, mx1, 1));
        mx1 = fmaxf(mx1, __shfl_xor_sync(FULL, mx1, 2));

        const float mnew0 = fmaxf(mrow0, mx0);
        const float mnew1 = fmaxf(mrow1, mx1);
        const float fac0  = __expf(mrow0 - mnew0);
        const float fac1  = __expf(mrow1 - mnew1);

        // ---- exp in place (S becomes P, kept in c-frag registers)
        float sum0 = 0.f, sum1 = 0.f;
#pragma unroll
        for (int j = 0; j < 8; j++) {
            S[j][0] = __expf(S[j][0] - mnew0);
            S[j][1] = __expf(S[j][1] - mnew0);
            S[j][2] = __expf(S[j][2] - mnew1);
            S[j][3] = __expf(S[j][3] - mnew1);
            sum0 += S[j][0] + S[j][1];
            sum1 += S[j][2] + S[j][3];
        }
        sum0 += __shfl_xor_sync(FULL, sum0, 1);
        sum0 += __shfl_xor_sync(FULL, sum0, 2);
        sum1 += __shfl_xor_sync(FULL, sum1, 1);
        sum1 += __shfl_xor_sync(FULL, sum1, 2);

        lrow0 = lrow0 * fac0 + sum0;
        lrow1 = lrow1 * fac1 + sum1;
        mrow0 = mnew0;
        mrow1 = mnew1;

#pragma unroll
        for (int j = 0; j < 8; j++) {
            O[j][0] *= fac0; O[j][1] *= fac0;
            O[j][2] *= fac1; O[j][3] *= fac1;
        }

        // ---- O += P @ V : c-frag -> a-frag via intra-quad shuffles
#pragma unroll
        for (int ks = 0; ks < 8; ks++) {
            const float e0 = __shfl_sync(FULL, S[ks][0], s0);
            const float o0 = __shfl_sync(FULL, S[ks][1], s0);
            const float e1 = __shfl_sync(FULL, S[ks][2], s0);
            const float o1 = __shfl_sync(FULL, S[ks][3], s0);
            const float e2 = __shfl_sync(FULL, S[ks][0], s1);
            const float o2 = __shfl_sync(FULL, S[ks][1], s1);
            const float e3 = __shfl_sync(FULL, S[ks][2], s1);
            const float o3 = __shfl_sync(FULL, S[ks][3], s1);
            float av[4];
            av[0] = odd ? o0 : e0;    // P[g   ][8ks+tig]
            av[1] = odd ? o1 : e1;    // P[g+8 ][8ks+tig]
            av[2] = odd ? o2 : e2;    // P[g   ][8ks+tig+4]
            av[3] = odd ? o3 : e3;    // P[g+8 ][8ks+tig+4]
            uint32_t ah[4], al[4];
            split4(av, ah, al);
            const int kk = ks * 8;
#pragma unroll
            for (int jn = 0; jn < 8; jn++) {
                const int c0 = (kk + tig) * VPAD + jn * 8 + g;
                const int c1 = (kk + tig + 4) * VPAD + jn * 8 + g;
                uint32_t bh[2] = { __float_as_uint(Vhi[c0]),
                                   __float_as_uint(Vhi[c1]) };
                uint32_t bl[2] = { __float_as_uint(Vlo[c0]),
                                   __float_as_uint(Vlo[c1]) };
                mma8(O[jn], ah, bh);
                mma8(O[jn], ah, bl);
                mma8(O[jn], al, bh);
            }
        }
        __syncthreads();   // before next tile overwrites K/V tiles
    }

    // ---- epilogue: normalize + store (float2)
    const float inv0 = 1.f / lrow0;
    const float inv1 = 1.f / lrow1;
    const int row0 = q0 + wm + g;
#pragma unroll
    for (int jn = 0; jn < 8; jn++) {
        const int col = h * DHEAD + jn * 8 + 2 * tig;
        float2 v0, v1;
        v0.x = O[jn][0] * inv0; v0.y = O[jn][1] * inv0;
        v1.x = O[jn][2] * inv1; v1.y = O[jn][3] * inv1;
        *(float2*)(out + ((size_t)b * SLEN + row0) * DMODEL + col)     = v0;
        *(float2*)(out + ((size_t)b * SLEN + row0 + 8) * DMODEL + col) = v1;
    }
}

// ---------------------------------------------------------------------------
extern "C" void kernel_launch(void* const* d_in, const int* in_sizes, int n_in,
                              void* d_out, int out_size)
{
    const float* Q    = (const float*)d_in[0];
    const float* K    = (const float*)d_in[1];
    const float* V    = (const float*)d_in[2];
    const int*   mask = (const int*)d_in[3];
    const float* Wq   = (const float*)d_in[4];
    const float* bq   = (const float*)d_in[5];
    const float* Wk   = (const float*)d_in[6];
    const float* bk   = (const float*)d_in[7];
    const float* Wv   = (const float*)d_in[8];
    const float* bv   = (const float*)d_in[9];
    float* out = (float*)d_out;

    float *qd, *kd, *vd;
    cudaGetSymbolAddress((void**)&qd, g_q);
    cudaGetSymbolAddress((void**)&kd, g_k);
    cudaGetSymbolAddress((void**)&vd, g_v);

    cudaFuncSetAttribute(proj_mma, cudaFuncAttributeMaxDynamicSharedMemorySize,
                         PROJ_SMEM);
    const dim3 pgrid(DMODEL / 128, (BATCH * SLEN) / 128, 3);
    proj_mma<<<pgrid, 256, PROJ_SMEM>>>(Q, K, V, Wq, Wk, Wv, bq, bk, bv,
                                        qd, kd, vd);

    cudaFuncSetAttribute(attn_mma, cudaFuncAttributeMaxDynamicSharedMemorySize,
                         ATTN_SMEM);
    const dim3 agrid(SLEN / 128, NHEAD, BATCH);
    attn_mma<<<agrid, 256, ATTN_SMEM>>>(mask, out);
}

// round 6
// speedup vs baseline: 2.7049x; 1.4165x over previous
#include <cuda_runtime.h>
#include <cuda_bf16.h>
#include <math.h>
#include <stdint.h>

#define BATCH  4
#define SLEN   2048
#define DMODEL 1024
#define NHEAD  16
#define DHEAD  64
#define ATT_SCALE 0.125f   // 1/sqrt(64)

// ---------------------------------------------------------------------------
// Device scratch (no cudaMalloc allowed)
// ---------------------------------------------------------------------------
__device__ float g_q[BATCH * SLEN * DMODEL];
__device__ float g_k[BATCH * SLEN * DMODEL];
__device__ float g_v[BATCH * SLEN * DMODEL];

// ---------------------------------------------------------------------------
// Helpers
// ---------------------------------------------------------------------------
// m16n8k16 bf16 MMA (portable warp-level tensor op, valid on base sm_103)
__device__ __forceinline__ void mma16(float c[4], const uint32_t a[4],
                                      const uint32_t b[2]) {
    asm volatile(
        "mma.sync.aligned.m16n8k16.row.col.f32.bf16.bf16.f32 "
        "{%0,%1,%2,%3}, {%4,%5,%6,%7}, {%8,%9}, {%0,%1,%2,%3};"
        : "+f"(c[0]), "+f"(c[1]), "+f"(c[2]), "+f"(c[3])
        : "r"(a[0]), "r"(a[1]), "r"(a[2]), "r"(a[3]),
          "r"(b[0]), "r"(b[1]));
}

// Split (x0, x1) into packed bf16x2 hi word + residual lo word (x0 -> low half)
__device__ __forceinline__ void split2(float x0, float x1, uint32_t& h,
                                       uint32_t& l) {
    __nv_bfloat162 hb = __floats2bfloat162_rn(x0, x1);
    const float2 hf = __bfloat1622float2(hb);
    __nv_bfloat162 lb = __floats2bfloat162_rn(x0 - hf.x, x1 - hf.y);
    h = *reinterpret_cast<uint32_t*>(&hb);
    l = *reinterpret_cast<uint32_t*>(&lb);
}

// ---------------------------------------------------------------------------
// Fused projection GEMMs (Q, K, V in one launch; blockIdx.z selects).
// Y[8192,1024] = X @ W + bias, bf16x3 split, CTA tile 128x128, BK=32.
// Smem word stride 20 (16 data + 4 pad) -> frag banks = all-distinct.
// ---------------------------------------------------------------------------
#define PSTR 20
#define PROJ_SMEM (4 * 128 * PSTR * 4)   // 40960 bytes

__global__ __launch_bounds__(256, 2)
void proj_mma(const float* __restrict__ X0, const float* __restrict__ X1,
              const float* __restrict__ X2,
              const float* __restrict__ W0, const float* __restrict__ W1,
              const float* __restrict__ W2,
              const float* __restrict__ b0, const float* __restrict__ b1,
              const float* __restrict__ b2,
              float* __restrict__ Y0, float* __restrict__ Y1,
              float* __restrict__ Y2)
{
    extern __shared__ uint32_t smw[];
    uint32_t* Ah = smw;                  // [128][PSTR] bf16x2 hi
    uint32_t* Al = Ah + 128 * PSTR;
    uint32_t* Bh = Al + 128 * PSTR;      // W^T, [128 n][PSTR]
    uint32_t* Bl = Bh + 128 * PSTR;

    const int z = blockIdx.z;
    const float* X    = (z == 0) ? X0 : (z == 1) ? X1 : X2;
    const float* W    = (z == 0) ? W0 : (z == 1) ? W1 : W2;
    const float* bias = (z == 0) ? b0 : (z == 1) ? b1 : b2;
    float*       Y    = (z == 0) ? Y0 : (z == 1) ? Y1 : Y2;

    const int tid  = threadIdx.x;
    const int lane = tid & 31;
    const int w    = tid >> 5;
    const int g    = lane >> 2;
    const int tig  = lane & 3;
    const int wm   = (w >> 2) * 64;
    const int wn   = (w & 3) * 32;
    const int m0   = blockIdx.y * 128;
    const int n0   = blockIdx.x * 128;

    float acc[4][4][4];
#pragma unroll
    for (int i = 0; i < 4; i++)
#pragma unroll
        for (int j = 0; j < 4; j++)
#pragma unroll
            for (int r = 0; r < 4; r++) acc[i][j][r] = 0.f;

    for (int k0 = 0; k0 < DMODEL; k0 += 32) {
        // ---- A tile (row-major), split to bf16 hi/lo packed pairs
#pragma unroll
        for (int it = 0; it < 4; it++) {
            const int idx = tid + it * 256;
            const int r = idx >> 3, c = (idx & 7) << 2;
            const float4 v = *(const float4*)(X + (size_t)(m0 + r) * DMODEL + k0 + c);
            uint32_t h0, l0, h1, l1;
            split2(v.x, v.y, h0, l0);
            split2(v.z, v.w, h1, l1);
            *(uint2*)&Ah[r * PSTR + (c >> 1)] = make_uint2(h0, h1);
            *(uint2*)&Al[r * PSTR + (c >> 1)] = make_uint2(l0, l1);
        }
        // ---- B tile: W[k][n] -> W^T[n][k]
#pragma unroll
        for (int it = 0; it < 4; it++) {
            const int idx = tid + it * 256;
            const int n  = idx & 127;
            const int k4 = (idx >> 7) << 2;
            float4 v;
            v.x = W[(size_t)(k0 + k4 + 0) * DMODEL + n0 + n];
            v.y = W[(size_t)(k0 + k4 + 1) * DMODEL + n0 + n];
            v.z = W[(size_t)(k0 + k4 + 2) * DMODEL + n0 + n];
            v.w = W[(size_t)(k0 + k4 + 3) * DMODEL + n0 + n];
            uint32_t h0, l0, h1, l1;
            split2(v.x, v.y, h0, l0);
            split2(v.z, v.w, h1, l1);
            *(uint2*)&Bh[n * PSTR + (k4 >> 1)] = make_uint2(h0, h1);
            *(uint2*)&Bl[n * PSTR + (k4 >> 1)] = make_uint2(l0, l1);
        }
        __syncthreads();

#pragma unroll
        for (int ks = 0; ks < 2; ks++) {
            const int off = ks * 8 + tig;
            uint32_t bh[4][2], bl[4][2];
#pragma unroll
            for (int j = 0; j < 4; j++) {
                const int nb = (wn + j * 8 + g) * PSTR + off;
                bh[j][0] = Bh[nb];  bh[j][1] = Bh[nb + 4];
                bl[j][0] = Bl[nb];  bl[j][1] = Bl[nb + 4];
            }
#pragma unroll
            for (int i = 0; i < 4; i++) {
                const int ra = (wm + i * 16 + g) * PSTR + off;
                uint32_t ah[4], al[4];
                ah[0] = Ah[ra];             ah[1] = Ah[ra + 8 * PSTR];
                ah[2] = Ah[ra + 4];         ah[3] = Ah[ra + 8 * PSTR + 4];
                al[0] = Al[ra];             al[1] = Al[ra + 8 * PSTR];
                al[2] = Al[ra + 4];         al[3] = Al[ra + 8 * PSTR + 4];
#pragma unroll
                for (int j = 0; j < 4; j++) {
                    mma16(acc[i][j], ah, bh[j]);
                    mma16(acc[i][j], ah, bl[j]);
                    mma16(acc[i][j], al, bh[j]);
                }
            }
        }
        __syncthreads();
    }

#pragma unroll
    for (int j = 0; j < 4; j++) {
        const int col = n0 + wn + j * 8 + 2 * tig;
        const float bx = bias[col], by = bias[col + 1];
#pragma unroll
        for (int i = 0; i < 4; i++) {
            const int r0 = m0 + wm + i * 16 + g;
            float2 v0, v1;
            v0.x = acc[i][j][0] + bx; v0.y = acc[i][j][1] + by;
            v1.x = acc[i][j][2] + bx; v1.y = acc[i][j][3] + by;
            *(float2*)(Y + (size_t)r0 * DMODEL + col)       = v0;
            *(float2*)(Y + (size_t)(r0 + 8) * DMODEL + col) = v1;
        }
    }
}

// ---------------------------------------------------------------------------
// Flash attention on bf16x3 tensor cores.
// CTA: 256 threads / 8 warps. Q tile = 128 rows (warp = 16), key tile = 64.
// Smem word stride 36 (32 data + 4 pad); V stored dim-major (transposed).
// P never leaves registers (c-frag -> a-frag is a pure in-thread cvt).
// ---------------------------------------------------------------------------
#define ASTR 36
#define ATTN_SMEM ((2 * 128 * ASTR + 4 * 64 * ASTR) * 4 + 64 * 4)

__global__ __launch_bounds__(256, 2)
void attn_mma(const int* __restrict__ mask, float* __restrict__ out)
{
    extern __shared__ uint32_t smw[];
    uint32_t* Qh = smw;                    // [128][ASTR] bf16x2 hi
    uint32_t* Ql = Qh + 128 * ASTR;
    uint32_t* Kh = Ql + 128 * ASTR;        // [64 key][ASTR]
    uint32_t* Kl = Kh + 64 * ASTR;
    uint32_t* Vh = Kl + 64 * ASTR;         // [64 dim][ASTR] (keys packed 2/word)
    uint32_t* Vl = Vh + 64 * ASTR;
    int*      msk = (int*)(Vl + 64 * ASTR);

    const int tid  = threadIdx.x;
    const int lane = tid & 31;
    const int w    = tid >> 5;
    const int g    = lane >> 2;
    const int tig  = lane & 3;
    const int wm   = w * 16;
    const int q0   = blockIdx.x << 7;
    const int h    = blockIdx.y;
    const int b    = blockIdx.z;

    const float* qb = g_q + (size_t)b * SLEN * DMODEL + h * DHEAD;
    const float* kb = g_k + (size_t)b * SLEN * DMODEL + h * DHEAD;
    const float* vb = g_v + (size_t)b * SLEN * DMODEL + h * DHEAD;
    const int*   mb = mask + b * SLEN;

    // ---- load Q tile once, split to bf16 hi/lo
    for (int i = tid; i < 2048; i += 256) {
        const int r = i >> 4, d = (i & 15) << 2;
        const float4 v = *(const float4*)(qb + (size_t)(q0 + r) * DMODEL + d);
        uint32_t h0, l0, h1, l1;
        split2(v.x, v.y, h0, l0);
        split2(v.z, v.w, h1, l1);
        *(uint2*)&Qh[r * ASTR + (d >> 1)] = make_uint2(h0, h1);
        *(uint2*)&Ql[r * ASTR + (d >> 1)] = make_uint2(l0, l1);
    }

    float O[8][4];
#pragma unroll
    for (int j = 0; j < 8; j++)
#pragma unroll
        for (int r = 0; r < 4; r++) O[j][r] = 0.f;
    float mrow0 = -1e30f, mrow1 = -1e30f, lrow0 = 0.f, lrow1 = 0.f;

    const unsigned FULL = 0xffffffffu;
    const int qrow0 = (wm + g) * ASTR;
    const int qrow1 = (wm + g + 8) * ASTR;

    __syncthreads();

    for (int k0 = 0; k0 < SLEN; k0 += 64) {
        // ---- fill K (key-major) and V (dim-major / transposed), split bf16
        for (int i = tid; i < 1024; i += 256) {
            const int r = i >> 4, d = (i & 15) << 2;
            const size_t gg = (size_t)(k0 + r) * DMODEL + d;
            const float4 kv = *(const float4*)(kb + gg);
            uint32_t h0, l0, h1, l1;
            split2(kv.x, kv.y, h0, l0);
            split2(kv.z, kv.w, h1, l1);
            *(uint2*)&Kh[r * ASTR + (d >> 1)] = make_uint2(h0, h1);
            *(uint2*)&Kl[r * ASTR + (d >> 1)] = make_uint2(l0, l1);

            const float4 vv = *(const float4*)(vb + gg);
            __nv_bfloat16* VhH = (__nv_bfloat16*)Vh;
            __nv_bfloat16* VlH = (__nv_bfloat16*)Vl;
            const float vf[4] = { vv.x, vv.y, vv.z, vv.w };
#pragma unroll
            for (int e = 0; e < 4; e++) {
                const __nv_bfloat16 hh = __float2bfloat16(vf[e]);
                const __nv_bfloat16 ll =
                    __float2bfloat16(vf[e] - __bfloat162float(hh));
                VhH[(d + e) * (2 * ASTR) + r] = hh;
                VlH[(d + e) * (2 * ASTR) + r] = ll;
            }
        }
        if (tid < 64) msk[tid] = mb[k0 + tid];
        __syncthreads();

        // ---- S = Q @ K^T (bf16x3)
        float S[8][4];
#pragma unroll
        for (int j = 0; j < 8; j++)
#pragma unroll
            for (int r = 0; r < 4; r++) S[j][r] = 0.f;

#pragma unroll
        for (int ks = 0; ks < 4; ks++) {
            const int off = ks * 8 + tig;
            uint32_t ah[4], al[4];
            ah[0] = Qh[qrow0 + off];     ah[1] = Qh[qrow1 + off];
            ah[2] = Qh[qrow0 + off + 4]; ah[3] = Qh[qrow1 + off + 4];
            al[0] = Ql[qrow0 + off];     al[1] = Ql[qrow1 + off];
            al[2] = Ql[qrow0 + off + 4]; al[3] = Ql[qrow1 + off + 4];
#pragma unroll
            for (int j = 0; j < 8; j++) {
                const int cb = (j * 8 + g) * ASTR + off;
                uint32_t bh[2] = { Kh[cb], Kh[cb + 4] };
                uint32_t bl[2] = { Kl[cb], Kl[cb + 4] };
                mma16(S[j], ah, bh);
                mma16(S[j], ah, bl);
                mma16(S[j], al, bh);
            }
        }

        // ---- scale + mask (registers)
        float mx0 = -1e30f, mx1 = -1e30f;
#pragma unroll
        for (int j = 0; j < 8; j++) {
            const int c = j * 8 + 2 * tig;
            const bool d0 = (msk[c] == 0);
            const bool d1 = (msk[c + 1] == 0);
            S[j][0] = d0 ? -1e9f : S[j][0] * ATT_SCALE;
            S[j][1] = d1 ? -1e9f : S[j][1] * ATT_SCALE;
            S[j][2] = d0 ? -1e9f : S[j][2] * ATT_SCALE;
            S[j][3] = d1 ? -1e9f : S[j][3] * ATT_SCALE;
            mx0 = fmaxf(mx0, fmaxf(S[j][0], S[j][1]));
            mx1 = fmaxf(mx1, fmaxf(S[j][2], S[j][3]));
        }
        mx0 = fmaxf(mx0, __shfl_xor_sync(FULL, mx0, 1));
        mx0 = fmaxf(mx0, __shfl_xor_sync(FULL, mx0, 2));
        mx1 = fmaxf(mx1, __shfl_xor_sync(FULL, mx1, 1));
        mx1 = fmaxf(mx1, __shfl_xor_sync(FULL, mx1, 2));

        const float mnew0 = fmaxf(mrow0, mx0);
        const float mnew1 = fmaxf(mrow1, mx1);
        const float fac0  = __expf(mrow0 - mnew0);
        const float fac1  = __expf(mrow1 - mnew1);

        // ---- exp in place (S becomes P), row sums
        float sum0 = 0.f, sum1 = 0.f;
#pragma unroll
        for (int j = 0; j < 8; j++) {
            S[j][0] = __expf(S[j][0] - mnew0);
            S[j][1] = __expf(S[j][1] - mnew0);
            S[j][2] = __expf(S[j][2] - mnew1);
            S[j][3] = __expf(S[j][3] - mnew1);
            sum0 += S[j][0] + S[j][1];
            sum1 += S[j][2] + S[j][3];
        }
        sum0 += __shfl_xor_sync(FULL, sum0, 1);
        sum0 += __shfl_xor_sync(FULL, sum0, 2);
        sum1 += __shfl_xor_sync(FULL, sum1, 1);
        sum1 += __shfl_xor_sync(FULL, sum1, 2);

        lrow0 = lrow0 * fac0 + sum0;
        lrow1 = lrow1 * fac1 + sum1;
        mrow0 = mnew0;
        mrow1 = mnew1;

#pragma unroll
        for (int j = 0; j < 8; j++) {
            O[j][0] *= fac0; O[j][1] *= fac0;
            O[j][2] *= fac1; O[j][3] *= fac1;
        }

        // ---- O += P @ V : c-frag converts straight to k16 a-frag (no shfl)
#pragma unroll
        for (int ks = 0; ks < 4; ks++) {
            uint32_t ah[4], al[4];
            split2(S[2 * ks][0],     S[2 * ks][1],     ah[0], al[0]);
            split2(S[2 * ks][2],     S[2 * ks][3],     ah[1], al[1]);
            split2(S[2 * ks + 1][0], S[2 * ks + 1][1], ah[2], al[2]);
            split2(S[2 * ks + 1][2], S[2 * ks + 1][3], ah[3], al[3]);
            const int off = ks * 8 + tig;
#pragma unroll
            for (int jn = 0; jn < 8; jn++) {
                const int vbI = (jn * 8 + g) * ASTR + off;
                uint32_t bh[2] = { Vh[vbI], Vh[vbI + 4] };
                uint32_t bl[2] = { Vl[vbI], Vl[vbI + 4] };
                mma16(O[jn], ah, bh);
                mma16(O[jn], ah, bl);
                mma16(O[jn], al, bh);
            }
        }
        __syncthreads();   // before next tile overwrites K/V tiles
    }

    // ---- epilogue: normalize + store (float2)
    const float inv0 = 1.f / lrow0;
    const float inv1 = 1.f / lrow1;
    const int row0 = q0 + wm + g;
#pragma unroll
    for (int jn = 0; jn < 8; jn++) {
        const int col = h * DHEAD + jn * 8 + 2 * tig;
        float2 v0, v1;
        v0.x = O[jn][0] * inv0; v0.y = O[jn][1] * inv0;
        v1.x = O[jn][2] * inv1; v1.y = O[jn][3] * inv1;
        *(float2*)(out + ((size_t)b * SLEN + row0) * DMODEL + col)     = v0;
        *(float2*)(out + ((size_t)b * SLEN + row0 + 8) * DMODEL + col) = v1;
    }
}

// ---------------------------------------------------------------------------
extern "C" void kernel_launch(void* const* d_in, const int* in_sizes, int n_in,
                              void* d_out, int out_size)
{
    const float* Q    = (const float*)d_in[0];
    const float* K    = (const float*)d_in[1];
    const float* V    = (const float*)d_in[2];
    const int*   mask = (const int*)d_in[3];
    const float* Wq   = (const float*)d_in[4];
    const float* bq   = (const float*)d_in[5];
    const float* Wk   = (const float*)d_in[6];
    const float* bk   = (const float*)d_in[7];
    const float* Wv   = (const float*)d_in[8];
    const float* bv   = (const float*)d_in[9];
    float* out = (float*)d_out;

    float *qd, *kd, *vd;
    cudaGetSymbolAddress((void**)&qd, g_q);
    cudaGetSymbolAddress((void**)&kd, g_k);
    cudaGetSymbolAddress((void**)&vd, g_v);

    cudaFuncSetAttribute(proj_mma, cudaFuncAttributeMaxDynamicSharedMemorySize,
                         PROJ_SMEM);
    const dim3 pgrid(DMODEL / 128, (BATCH * SLEN) / 128, 3);
    proj_mma<<<pgrid, 256, PROJ_SMEM>>>(Q, K, V, Wq, Wk, Wv, bq, bk, bv,
                                        qd, kd, vd);

    cudaFuncSetAttribute(attn_mma, cudaFuncAttributeMaxDynamicSharedMemorySize,
                         ATTN_SMEM);
    const dim3 agrid(SLEN / 128, NHEAD, BATCH);
    attn_mma<<<agrid, 256, ATTN_SMEM>>>(mask, out);
}

// round 7
// speedup vs baseline: 3.1307x; 1.1574x over previous
#include <cuda_runtime.h>
#include <cuda_bf16.h>
#include <math.h>
#include <stdint.h>

#define BATCH  4
#define SLEN   2048
#define DMODEL 1024
#define NHEAD  16
#define DHEAD  64
#define ATT_SCALE 0.125f   // 1/sqrt(64)

// ---------------------------------------------------------------------------
// Device scratch (no cudaMalloc allowed)
// ---------------------------------------------------------------------------
__device__ float g_q[BATCH * SLEN * DMODEL];
__device__ float g_k[BATCH * SLEN * DMODEL];
__device__ float g_v[BATCH * SLEN * DMODEL];

// ---------------------------------------------------------------------------
// Helpers
// ---------------------------------------------------------------------------
__device__ __forceinline__ void mma16(float c[4], const uint32_t a[4],
                                      const uint32_t b[2]) {
    asm volatile(
        "mma.sync.aligned.m16n8k16.row.col.f32.bf16.bf16.f32 "
        "{%0,%1,%2,%3}, {%4,%5,%6,%7}, {%8,%9}, {%0,%1,%2,%3};"
        : "+f"(c[0]), "+f"(c[1]), "+f"(c[2]), "+f"(c[3])
        : "r"(a[0]), "r"(a[1]), "r"(a[2]), "r"(a[3]),
          "r"(b[0]), "r"(b[1]));
}

__device__ __forceinline__ void ldsm4(uint32_t r[4], uint32_t addr) {
    asm volatile(
        "ldmatrix.sync.aligned.m8n8.x4.shared.b16 {%0,%1,%2,%3}, [%4];"
        : "=r"(r[0]), "=r"(r[1]), "=r"(r[2]), "=r"(r[3]) : "r"(addr));
}

__device__ __forceinline__ void ldsm4t(uint32_t r[4], uint32_t addr) {
    asm volatile(
        "ldmatrix.sync.aligned.m8n8.x4.trans.shared.b16 {%0,%1,%2,%3}, [%4];"
        : "=r"(r[0]), "=r"(r[1]), "=r"(r[2]), "=r"(r[3]) : "r"(addr));
}

__device__ __forceinline__ uint32_t sptr(const void* p) {
    return (uint32_t)__cvta_generic_to_shared(p);
}

// Split (x0, x1) into packed bf16x2 hi word + residual lo word (x0 -> low half)
__device__ __forceinline__ void split2(float x0, float x1, uint32_t& h,
                                       uint32_t& l) {
    __nv_bfloat162 hb = __floats2bfloat162_rn(x0, x1);
    const float2 hf = __bfloat1622float2(hb);
    __nv_bfloat162 lb = __floats2bfloat162_rn(x0 - hf.x, x1 - hf.y);
    h = *reinterpret_cast<uint32_t*>(&hb);
    l = *reinterpret_cast<uint32_t*>(&lb);
}

// ---------------------------------------------------------------------------
// Fused projection GEMMs (Q, K, V in one launch; blockIdx.z selects).
// bf16x3 split, CTA tile 128x128, BK=32, ldmatrix fragment loads.
// ---------------------------------------------------------------------------
#define PSTR 20
#define PROJ_SMEM (4 * 128 * PSTR * 4)   // 40960 bytes

__global__ __launch_bounds__(256, 2)
void proj_mma(const float* __restrict__ X0, const float* __restrict__ X1,
              const float* __restrict__ X2,
              const float* __restrict__ W0, const float* __restrict__ W1,
              const float* __restrict__ W2,
              const float* __restrict__ b0, const float* __restrict__ b1,
              const float* __restrict__ b2,
              float* __restrict__ Y0, float* __restrict__ Y1,
              float* __restrict__ Y2)
{
    extern __shared__ uint32_t smw[];
    uint32_t* Ah = smw;                  // [128][PSTR] bf16x2 hi
    uint32_t* Al = Ah + 128 * PSTR;
    uint32_t* Bh = Al + 128 * PSTR;      // W^T, [128 n][PSTR]
    uint32_t* Bl = Bh + 128 * PSTR;

    const int z = blockIdx.z;
    const float* X    = (z == 0) ? X0 : (z == 1) ? X1 : X2;
    const float* W    = (z == 0) ? W0 : (z == 1) ? W1 : W2;
    const float* bias = (z == 0) ? b0 : (z == 1) ? b1 : b2;
    float*       Y    = (z == 0) ? Y0 : (z == 1) ? Y1 : Y2;

    const int tid  = threadIdx.x;
    const int lane = tid & 31;
    const int w    = tid >> 5;
    const int g    = lane >> 2;
    const int tig  = lane & 3;
    const int wm   = (w >> 2) * 64;
    const int wn   = (w & 3) * 32;
    const int m0   = blockIdx.y * 128;
    const int n0   = blockIdx.x * 128;

    // ldmatrix lane-address components
    const int lane15  = lane & 15;
    const int halfsel = (lane >> 4) & 1;              // x4 col-half select
    const int krow    = (lane & 7) + ((lane & 16) >> 1);  // b-frag row in j-pair
    const int kcol    = (lane & 8) >> 1;              // b-frag col word

    const uint32_t pa = sptr(Ah) + ((wm + lane15) * PSTR + halfsel * 4) * 4;
    const uint32_t pb = sptr(Bh) + ((wn + krow) * PSTR + kcol) * 4;
    const uint32_t ALO = 128 * PSTR * 4;
    const uint32_t BLO = 128 * PSTR * 4;

    float acc[4][4][4];
#pragma unroll
    for (int i = 0; i < 4; i++)
#pragma unroll
        for (int j = 0; j < 4; j++)
#pragma unroll
            for (int r = 0; r < 4; r++) acc[i][j][r] = 0.f;

    for (int k0 = 0; k0 < DMODEL; k0 += 32) {
#pragma unroll
        for (int it = 0; it < 4; it++) {
            const int idx = tid + it * 256;
            const int r = idx >> 3, c = (idx & 7) << 2;
            const float4 v = *(const float4*)(X + (size_t)(m0 + r) * DMODEL + k0 + c);
            uint32_t h0, l0, h1, l1;
            split2(v.x, v.y, h0, l0);
            split2(v.z, v.w, h1, l1);
            *(uint2*)&Ah[r * PSTR + (c >> 1)] = make_uint2(h0, h1);
            *(uint2*)&Al[r * PSTR + (c >> 1)] = make_uint2(l0, l1);
        }
#pragma unroll
        for (int it = 0; it < 4; it++) {
            const int idx = tid + it * 256;
            const int n  = idx & 127;
            const int k4 = (idx >> 7) << 2;
            float4 v;
            v.x = W[(size_t)(k0 + k4 + 0) * DMODEL + n0 + n];
            v.y = W[(size_t)(k0 + k4 + 1) * DMODEL + n0 + n];
            v.z = W[(size_t)(k0 + k4 + 2) * DMODEL + n0 + n];
            v.w = W[(size_t)(k0 + k4 + 3) * DMODEL + n0 + n];
            uint32_t h0, l0, h1, l1;
            split2(v.x, v.y, h0, l0);
            split2(v.z, v.w, h1, l1);
            *(uint2*)&Bh[n * PSTR + (k4 >> 1)] = make_uint2(h0, h1);
            *(uint2*)&Bl[n * PSTR + (k4 >> 1)] = make_uint2(l0, l1);
        }
        __syncthreads();

#pragma unroll
        for (int ks = 0; ks < 2; ks++) {
            uint32_t bh0[4], bl0[4], bh1[4], bl1[4];
            ldsm4(bh0, pb + ks * 32);
            ldsm4(bl0, pb + ks * 32 + BLO);
            ldsm4(bh1, pb + 16 * PSTR * 4 + ks * 32);
            ldsm4(bl1, pb + 16 * PSTR * 4 + ks * 32 + BLO);
#pragma unroll
            for (int i = 0; i < 4; i++) {
                uint32_t ah[4], al[4];
                ldsm4(ah, pa + i * 16 * PSTR * 4 + ks * 32);
                ldsm4(al, pa + i * 16 * PSTR * 4 + ks * 32 + ALO);
                mma16(acc[i][0], ah, bh0);     mma16(acc[i][0], ah, bl0);
                mma16(acc[i][0], al, bh0);
                mma16(acc[i][1], ah, bh0 + 2); mma16(acc[i][1], ah, bl0 + 2);
                mma16(acc[i][1], al, bh0 + 2);
                mma16(acc[i][2], ah, bh1);     mma16(acc[i][2], ah, bl1);
                mma16(acc[i][2], al, bh1);
                mma16(acc[i][3], ah, bh1 + 2); mma16(acc[i][3], ah, bl1 + 2);
                mma16(acc[i][3], al, bh1 + 2);
            }
        }
        __syncthreads();
    }

#pragma unroll
    for (int j = 0; j < 4; j++) {
        const int col = n0 + wn + j * 8 + 2 * tig;
        const float bx = bias[col], by = bias[col + 1];
#pragma unroll
        for (int i = 0; i < 4; i++) {
            const int r0 = m0 + wm + i * 16 + g;
            float2 v0, v1;
            v0.x = acc[i][j][0] + bx; v0.y = acc[i][j][1] + by;
            v1.x = acc[i][j][2] + bx; v1.y = acc[i][j][3] + by;
            *(float2*)(Y + (size_t)r0 * DMODEL + col)       = v0;
            *(float2*)(Y + (size_t)(r0 + 8) * DMODEL + col) = v1;
        }
    }
}

// ---------------------------------------------------------------------------
// Flash attention, bf16x3 tensor cores, ldmatrix everywhere.
// V stored key-major (same fill as K); PV b-frags come via ldmatrix.trans.
// CTA: 256 threads / 8 warps. Q tile = 128 rows (warp = 16), key tile = 64.
// ---------------------------------------------------------------------------
#define ASTR 36
#define ATTN_SMEM ((2 * 128 * ASTR + 4 * 64 * ASTR) * 4 + 64 * 4)

__global__ __launch_bounds__(256, 2)
void attn_mma(const int* __restrict__ mask, float* __restrict__ out)
{
    extern __shared__ uint32_t smw[];
    uint32_t* Qh = smw;                    // [128][ASTR] bf16x2 hi
    uint32_t* Ql = Qh + 128 * ASTR;
    uint32_t* Kh = Ql + 128 * ASTR;        // [64 key][ASTR]
    uint32_t* Kl = Kh + 64 * ASTR;
    uint32_t* Vh = Kl + 64 * ASTR;         // [64 key][ASTR] (key-major!)
    uint32_t* Vl = Vh + 64 * ASTR;
    int*      msk = (int*)(Vl + 64 * ASTR);

    const int tid  = threadIdx.x;
    const int lane = tid & 31;
    const int w    = tid >> 5;
    const int tig  = lane & 3;
    const int wm   = w * 16;
    const int q0   = blockIdx.x << 7;
    const int h    = blockIdx.y;
    const int b    = blockIdx.z;

    const float* qb = g_q + (size_t)b * SLEN * DMODEL + h * DHEAD;
    const float* kb = g_k + (size_t)b * SLEN * DMODEL + h * DHEAD;
    const float* vb = g_v + (size_t)b * SLEN * DMODEL + h * DHEAD;
    const int*   mb = mask + b * SLEN;

    // ldmatrix lane-address components
    const int lane15  = lane & 15;
    const int halfsel = (lane >> 4) & 1;
    const int krow    = (lane & 7) + ((lane & 16) >> 1);
    const int kcol    = (lane & 8) >> 1;

    const uint32_t qa = sptr(Qh) + ((wm + lane15) * ASTR + halfsel * 4) * 4;
    const uint32_t ka = sptr(Kh) + (krow * ASTR + kcol) * 4;
    const uint32_t va = sptr(Vh) + (lane15 * ASTR + halfsel * 4) * 4;
    const uint32_t QLO = 128 * ASTR * 4;
    const uint32_t KLO = 64 * ASTR * 4;
    const uint32_t VLO = 64 * ASTR * 4;

    // ---- load Q tile once, split to bf16 hi/lo
    for (int i = tid; i < 2048; i += 256) {
        const int r = i >> 4, d = (i & 15) << 2;
        const float4 v = *(const float4*)(qb + (size_t)(q0 + r) * DMODEL + d);
        uint32_t h0, l0, h1, l1;
        split2(v.x, v.y, h0, l0);
        split2(v.z, v.w, h1, l1);
        *(uint2*)&Qh[r * ASTR + (d >> 1)] = make_uint2(h0, h1);
        *(uint2*)&Ql[r * ASTR + (d >> 1)] = make_uint2(l0, l1);
    }

    float O[8][4];
#pragma unroll
    for (int j = 0; j < 8; j++)
#pragma unroll
        for (int r = 0; r < 4; r++) O[j][r] = 0.f;
    float mrow0 = -1e30f, mrow1 = -1e30f, lrow0 = 0.f, lrow1 = 0.f;

    const unsigned FULL = 0xffffffffu;

    __syncthreads();

    for (int k0 = 0; k0 < SLEN; k0 += 64) {
        // ---- fill K and V, both key-major, split bf16 (vectorized stores)
        for (int i = tid; i < 1024; i += 256) {
            const int r = i >> 4, d = (i & 15) << 2;
            const size_t gg = (size_t)(k0 + r) * DMODEL + d;
            const float4 kv = *(const float4*)(kb + gg);
            uint32_t h0, l0, h1, l1;
            split2(kv.x, kv.y, h0, l0);
            split2(kv.z, kv.w, h1, l1);
            *(uint2*)&Kh[r * ASTR + (d >> 1)] = make_uint2(h0, h1);
            *(uint2*)&Kl[r * ASTR + (d >> 1)] = make_uint2(l0, l1);
            const float4 vv = *(const float4*)(vb + gg);
            split2(vv.x, vv.y, h0, l0);
            split2(vv.z, vv.w, h1, l1);
            *(uint2*)&Vh[r * ASTR + (d >> 1)] = make_uint2(h0, h1);
            *(uint2*)&Vl[r * ASTR + (d >> 1)] = make_uint2(l0, l1);
        }
        if (tid < 64) msk[tid] = mb[k0 + tid];
        __syncthreads();

        // ---- S = Q @ K^T (bf16x3, ldmatrix frags)
        float S[8][4];
#pragma unroll
        for (int j = 0; j < 8; j++)
#pragma unroll
            for (int r = 0; r < 4; r++) S[j][r] = 0.f;

#pragma unroll
        for (int ks = 0; ks < 4; ks++) {
            uint32_t ah[4], al[4];
            ldsm4(ah, qa + ks * 32);
            ldsm4(al, qa + ks * 32 + QLO);
#pragma unroll
            for (int jp = 0; jp < 4; jp++) {
                uint32_t bh[4], bl[4];
                const uint32_t kaddr = ka + jp * 16 * ASTR * 4 + ks * 32;
                ldsm4(bh, kaddr);
                ldsm4(bl, kaddr + KLO);
                mma16(S[2 * jp], ah, bh);         mma16(S[2 * jp], ah, bl);
                mma16(S[2 * jp], al, bh);
                mma16(S[2 * jp + 1], ah, bh + 2); mma16(S[2 * jp + 1], ah, bl + 2);
                mma16(S[2 * jp + 1], al, bh + 2);
            }
        }

        // ---- scale + mask (registers)
        float mx0 = -1e30f, mx1 = -1e30f;
#pragma unroll
        for (int j = 0; j < 8; j++) {
            const int c = j * 8 + 2 * tig;
            const bool d0 = (msk[c] == 0);
            const bool d1 = (msk[c + 1] == 0);
            S[j][0] = d0 ? -1e9f : S[j][0] * ATT_SCALE;
            S[j][1] = d1 ? -1e9f : S[j][1] * ATT_SCALE;
            S[j][2] = d0 ? -1e9f : S[j][2] * ATT_SCALE;
            S[j][3] = d1 ? -1e9f : S[j][3] * ATT_SCALE;
            mx0 = fmaxf(mx0, fmaxf(S[j][0], S[j][1]));
            mx1 = fmaxf(mx1, fmaxf(S[j][2], S[j][3]));
        }
        mx0 = fmaxf(mx0, __shfl_xor_sync(FULL, mx0, 1));
        mx0 = fmaxf(mx0, __shfl_xor_sync(FULL, mx0, 2));
        mx1 = fmaxf(mx1, __shfl_xor_sync(FULL, mx1, 1));
        mx1 = fmaxf(mx1, __shfl_xor_sync(FULL, mx1, 2));

        const float mnew0 = fmaxf(mrow0, mx0);
        const float mnew1 = fmaxf(mrow1, mx1);
        const float fac0  = __expf(mrow0 - mnew0);
        const float fac1  = __expf(mrow1 - mnew1);

        // ---- exp in place (S becomes P), row sums
        float sum0 = 0.f, sum1 = 0.f;
#pragma unroll
        for (int j = 0; j < 8; j++) {
            S[j][0] = __expf(S[j][0] - mnew0);
            S[j][1] = __expf(S[j][1] - mnew0);
            S[j][2] = __expf(S[j][2] - mnew1);
            S[j][3] = __expf(S[j][3] - mnew1);
            sum0 += S[j][0] + S[j][1];
            sum1 += S[j][2] + S[j][3];
        }
        sum0 += __shfl_xor_sync(FULL, sum0, 1);
        sum0 += __shfl_xor_sync(FULL, sum0, 2);
        sum1 += __shfl_xor_sync(FULL, sum1, 1);
        sum1 += __shfl_xor_sync(FULL, sum1, 2);

        lrow0 = lrow0 * fac0 + sum0;
        lrow1 = lrow1 * fac1 + sum1;
        mrow0 = mnew0;
        mrow1 = mnew1;

#pragma unroll
        for (int j = 0; j < 8; j++) {
            O[j][0] *= fac0; O[j][1] *= fac0;
            O[j][2] *= fac1; O[j][3] *= fac1;
        }

        // ---- O += P @ V : P c-frag -> a-frag in-thread; V via ldmatrix.trans
#pragma unroll
        for (int ks = 0; ks < 4; ks++) {
            uint32_t ah[4], al[4];
            split2(S[2 * ks][0],     S[2 * ks][1],     ah[0], al[0]);
            split2(S[2 * ks][2],     S[2 * ks][3],     ah[1], al[1]);
            split2(S[2 * ks + 1][0], S[2 * ks + 1][1], ah[2], al[2]);
            split2(S[2 * ks + 1][2], S[2 * ks + 1][3], ah[3], al[3]);
#pragma unroll
            for (int jnp = 0; jnp < 4; jnp++) {
                uint32_t bh[4], bl[4];
                const uint32_t vaddr = va + ks * 16 * ASTR * 4 + jnp * 32;
                ldsm4t(bh, vaddr);
                ldsm4t(bl, vaddr + VLO);
                mma16(O[2 * jnp], ah, bh);         mma16(O[2 * jnp], ah, bl);
                mma16(O[2 * jnp], al, bh);
                mma16(O[2 * jnp + 1], ah, bh + 2); mma16(O[2 * jnp + 1], ah, bl + 2);
                mma16(O[2 * jnp + 1], al, bh + 2);
            }
        }
        __syncthreads();   // before next tile overwrites K/V tiles
    }

    // ---- epilogue: normalize + store (float2)
    const int g2 = (lane >> 2);
    const float inv0 = 1.f / lrow0;
    const float inv1 = 1.f / lrow1;
    const int row0 = q0 + wm + g2;
#pragma unroll
    for (int jn = 0; jn < 8; jn++) {
        const int col = h * DHEAD + jn * 8 + 2 * tig;
        float2 v0, v1;
        v0.x = O[jn][0] * inv0; v0.y = O[jn][1] * inv0;
        v1.x = O[jn][2] * inv1; v1.y = O[jn][3] * inv1;
        *(float2*)(out + ((size_t)b * SLEN + row0) * DMODEL + col)     = v0;
        *(float2*)(out + ((size_t)b * SLEN + row0 + 8) * DMODEL + col) = v1;
    }
}

// ---------------------------------------------------------------------------
extern "C" void kernel_launch(void* const* d_in, const int* in_sizes, int n_in,
                              void* d_out, int out_size)
{
    const float* Q    = (const float*)d_in[0];
    const float* K    = (const float*)d_in[1];
    const float* V    = (const float*)d_in[2];
    const int*   mask = (const int*)d_in[3];
    const float* Wq   = (const float*)d_in[4];
    const float* bq   = (const float*)d_in[5];
    const float* Wk   = (const float*)d_in[6];
    const float* bk   = (const float*)d_in[7];
    const float* Wv   = (const float*)d_in[8];
    const float* bv   = (const float*)d_in[9];
    float* out = (float*)d_out;

    float *qd, *kd, *vd;
    cudaGetSymbolAddress((void**)&qd, g_q);
    cudaGetSymbolAddress((void**)&kd, g_k);
    cudaGetSymbolAddress((void**)&vd, g_v);

    cudaFuncSetAttribute(proj_mma, cudaFuncAttributeMaxDynamicSharedMemorySize,
                         PROJ_SMEM);
    const dim3 pgrid(DMODEL / 128, (BATCH * SLEN) / 128, 3);
    proj_mma<<<pgrid, 256, PROJ_SMEM>>>(Q, K, V, Wq, Wk, Wv, bq, bk, bv,
                                        qd, kd, vd);

    cudaFuncSetAttribute(attn_mma, cudaFuncAttributeMaxDynamicSharedMemorySize,
                         ATTN_SMEM);
    const dim3 agrid(SLEN / 128, NHEAD, BATCH);
    attn_mma<<<agrid, 256, ATTN_SMEM>>>(mask, out);
}

// round 8
// speedup vs baseline: 5.3951x; 1.7233x over previous
#include <cuda_runtime.h>
#include <cuda_bf16.h>
#include <math.h>
#include <stdint.h>

#define BATCH  4
#define SLEN   2048
#define DMODEL 1024
#define NHEAD  16
#define DHEAD  64
#define ATT_SCALE 0.125f   // 1/sqrt(64)

// ---------------------------------------------------------------------------
// Device scratch (no cudaMalloc allowed)
// ---------------------------------------------------------------------------
__device__ float g_q[BATCH * SLEN * DMODEL];
__device__ float g_k[BATCH * SLEN * DMODEL];   // packed (valid keys first)
__device__ float g_v[BATCH * SLEN * DMODEL];   // packed
__device__ int   g_idx[BATCH * SLEN];          // packed j -> original key
__device__ int   g_nv[BATCH];                  // valid-key count per batch

// ---------------------------------------------------------------------------
// Helpers
// ---------------------------------------------------------------------------
__device__ __forceinline__ void mma16(float c[4], const uint32_t a[4],
                                      const uint32_t b[2]) {
    asm volatile(
        "mma.sync.aligned.m16n8k16.row.col.f32.bf16.bf16.f32 "
        "{%0,%1,%2,%3}, {%4,%5,%6,%7}, {%8,%9}, {%0,%1,%2,%3};"
        : "+f"(c[0]), "+f"(c[1]), "+f"(c[2]), "+f"(c[3])
        : "r"(a[0]), "r"(a[1]), "r"(a[2]), "r"(a[3]),
          "r"(b[0]), "r"(b[1]));
}

__device__ __forceinline__ void ldsm4(uint32_t r[4], uint32_t addr) {
    asm volatile(
        "ldmatrix.sync.aligned.m8n8.x4.shared.b16 {%0,%1,%2,%3}, [%4];"
        : "=r"(r[0]), "=r"(r[1]), "=r"(r[2]), "=r"(r[3]) : "r"(addr));
}

__device__ __forceinline__ void ldsm4t(uint32_t r[4], uint32_t addr) {
    asm volatile(
        "ldmatrix.sync.aligned.m8n8.x4.trans.shared.b16 {%0,%1,%2,%3}, [%4];"
        : "=r"(r[0]), "=r"(r[1]), "=r"(r[2]), "=r"(r[3]) : "r"(addr));
}

__device__ __forceinline__ uint32_t sptr(const void* p) {
    return (uint32_t)__cvta_generic_to_shared(p);
}

__device__ __forceinline__ void split2(float x0, float x1, uint32_t& h,
                                       uint32_t& l) {
    __nv_bfloat162 hb = __floats2bfloat162_rn(x0, x1);
    const float2 hf = __bfloat1622float2(hb);
    __nv_bfloat162 lb = __floats2bfloat162_rn(x0 - hf.x, x1 - hf.y);
    h = *reinterpret_cast<uint32_t*>(&hb);
    l = *reinterpret_cast<uint32_t*>(&lb);
}

// ---------------------------------------------------------------------------
// Mask compaction: per batch, prefix-scan the key-padding mask.
// ---------------------------------------------------------------------------
__global__ __launch_bounds__(256)
void compact_mask(const int* __restrict__ mask)
{
    __shared__ int part[256];
    const int b   = blockIdx.x;
    const int tid = threadIdx.x;
    const int* mb = mask + b * SLEN;

    int loc[8];
    int cnt = 0;
#pragma unroll
    for (int e = 0; e < 8; e++) {
        loc[e] = cnt;
        cnt += (mb[tid * 8 + e] != 0);
    }
    part[tid] = cnt;
    __syncthreads();
    // Hillis-Steele inclusive scan over 256 partials
#pragma unroll
    for (int off = 1; off < 256; off <<= 1) {
        const int v = (tid >= off) ? part[tid - off] : 0;
        __syncthreads();
        part[tid] += v;
        __syncthreads();
    }
    const int excl = part[tid] - cnt;
#pragma unroll
    for (int e = 0; e < 8; e++) {
        if (mb[tid * 8 + e] != 0)
            g_idx[b * SLEN + excl + loc[e]] = tid * 8 + e;
    }
    const int total = part[255];
    if (tid == 0) g_nv[b] = total;
    __syncthreads();
    for (int j = total + tid; j < SLEN; j += 256)
        g_idx[b * SLEN + j] = 0;
}

// ---------------------------------------------------------------------------
// Fused projection GEMMs. z=0: Q (direct rows). z=1/2: K/V with row gather
// through g_idx into PACKED outputs; tiles beyond nv[b] exit early.
// bf16x3 split, CTA tile 128x128, BK=32, ldmatrix fragment loads.
// ---------------------------------------------------------------------------
#define PSTR 20
#define PROJ_SMEM (4 * 128 * PSTR * 4)   // 40960 bytes

__global__ __launch_bounds__(256, 2)
void proj_mma(const float* __restrict__ X0, const float* __restrict__ X1,
              const float* __restrict__ X2,
              const float* __restrict__ W0, const float* __restrict__ W1,
              const float* __restrict__ W2,
              const float* __restrict__ b0, const float* __restrict__ b1,
              const float* __restrict__ b2,
              float* __restrict__ Y0, float* __restrict__ Y1,
              float* __restrict__ Y2)
{
    extern __shared__ uint32_t smw[];
    uint32_t* Ah = smw;
    uint32_t* Al = Ah + 128 * PSTR;
    uint32_t* Bh = Al + 128 * PSTR;
    uint32_t* Bl = Bh + 128 * PSTR;

    const int z = blockIdx.z;
    const float* X    = (z == 0) ? X0 : (z == 1) ? X1 : X2;
    const float* W    = (z == 0) ? W0 : (z == 1) ? W1 : W2;
    const float* bias = (z == 0) ? b0 : (z == 1) ? b1 : b2;
    float*       Y    = (z == 0) ? Y0 : (z == 1) ? Y1 : Y2;

    const int m0   = blockIdx.y * 128;
    const int n0   = blockIdx.x * 128;
    const int bb   = m0 >> 11;             // batch of this row tile
    const int mloc = m0 & 2047;

    const int nvb = (z == 0) ? SLEN : g_nv[bb];
    if (mloc >= nvb) return;               // fully-invalid K/V tile
    const int* idxb = g_idx + bb * SLEN;

    const int tid  = threadIdx.x;
    const int lane = tid & 31;
    const int w    = tid >> 5;
    const int g    = lane >> 2;
    const int tig  = lane & 3;
    const int wm   = (w >> 2) * 64;
    const int wn   = (w & 3) * 32;

    const int lane15  = lane & 15;
    const int halfsel = (lane >> 4) & 1;
    const int krow    = (lane & 7) + ((lane & 16) >> 1);
    const int kcol    = (lane & 8) >> 1;

    const uint32_t pa = sptr(Ah) + ((wm + lane15) * PSTR + halfsel * 4) * 4;
    const uint32_t pb = sptr(Bh) + ((wn + krow) * PSTR + kcol) * 4;
    const uint32_t ALO = 128 * PSTR * 4;
    const uint32_t BLO = 128 * PSTR * 4;

    // source row for each of this thread's 4 A-tile rows (gathered for K/V)
    int srow[4];
#pragma unroll
    for (int it = 0; it < 4; it++) {
        const int r = (tid + it * 256) >> 3;
        if (z == 0) srow[it] = m0 + r;
        else {
            const int j = mloc + r;
            srow[it] = (bb << 11) + ((j < nvb) ? idxb[j] : idxb[0]);
        }
    }

    float acc[4][4][4];
#pragma unroll
    for (int i = 0; i < 4; i++)
#pragma unroll
        for (int j = 0; j < 4; j++)
#pragma unroll
            for (int r = 0; r < 4; r++) acc[i][j][r] = 0.f;

    for (int k0 = 0; k0 < DMODEL; k0 += 32) {
#pragma unroll
        for (int it = 0; it < 4; it++) {
            const int idx = tid + it * 256;
            const int r = idx >> 3, c = (idx & 7) << 2;
            const float4 v = *(const float4*)(X + (size_t)srow[it] * DMODEL + k0 + c);
            uint32_t h0, l0, h1, l1;
            split2(v.x, v.y, h0, l0);
            split2(v.z, v.w, h1, l1);
            *(uint2*)&Ah[r * PSTR + (c >> 1)] = make_uint2(h0, h1);
            *(uint2*)&Al[r * PSTR + (c >> 1)] = make_uint2(l0, l1);
        }
#pragma unroll
        for (int it = 0; it < 4; it++) {
            const int idx = tid + it * 256;
            const int n  = idx & 127;
            const int k4 = (idx >> 7) << 2;
            float4 v;
            v.x = W[(size_t)(k0 + k4 + 0) * DMODEL + n0 + n];
            v.y = W[(size_t)(k0 + k4 + 1) * DMODEL + n0 + n];
            v.z = W[(size_t)(k0 + k4 + 2) * DMODEL + n0 + n];
            v.w = W[(size_t)(k0 + k4 + 3) * DMODEL + n0 + n];
            uint32_t h0, l0, h1, l1;
            split2(v.x, v.y, h0, l0);
            split2(v.z, v.w, h1, l1);
            *(uint2*)&Bh[n * PSTR + (k4 >> 1)] = make_uint2(h0, h1);
            *(uint2*)&Bl[n * PSTR + (k4 >> 1)] = make_uint2(l0, l1);
        }
        __syncthreads();

#pragma unroll
        for (int ks = 0; ks < 2; ks++) {
            uint32_t bh0[4], bl0[4], bh1[4], bl1[4];
            ldsm4(bh0, pb + ks * 32);
            ldsm4(bl0, pb + ks * 32 + BLO);
            ldsm4(bh1, pb + 16 * PSTR * 4 + ks * 32);
            ldsm4(bl1, pb + 16 * PSTR * 4 + ks * 32 + BLO);
#pragma unroll
            for (int i = 0; i < 4; i++) {
                uint32_t ah[4], al[4];
                ldsm4(ah, pa + i * 16 * PSTR * 4 + ks * 32);
                ldsm4(al, pa + i * 16 * PSTR * 4 + ks * 32 + ALO);
                mma16(acc[i][0], ah, bh0);     mma16(acc[i][0], ah, bl0);
                mma16(acc[i][0], al, bh0);
                mma16(acc[i][1], ah, bh0 + 2); mma16(acc[i][1], ah, bl0 + 2);
                mma16(acc[i][1], al, bh0 + 2);
                mma16(acc[i][2], ah, bh1);     mma16(acc[i][2], ah, bl1);
                mma16(acc[i][2], al, bh1);
                mma16(acc[i][3], ah, bh1 + 2); mma16(acc[i][3], ah, bl1 + 2);
                mma16(acc[i][3], al, bh1 + 2);
            }
        }
        __syncthreads();
    }

#pragma unroll
    for (int j = 0; j < 4; j++) {
        const int col = n0 + wn + j * 8 + 2 * tig;
        const float bx = bias[col], by = bias[col + 1];
#pragma unroll
        for (int i = 0; i < 4; i++) {
            const int r0 = m0 + wm + i * 16 + g;
            float2 v0, v1;
            v0.x = acc[i][j][0] + bx; v0.y = acc[i][j][1] + by;
            v1.x = acc[i][j][2] + bx; v1.y = acc[i][j][3] + by;
            *(float2*)(Y + (size_t)r0 * DMODEL + col)       = v0;
            *(float2*)(Y + (size_t)(r0 + 8) * DMODEL + col) = v1;
        }
    }
}

// ---------------------------------------------------------------------------
// Flash attention over PACKED keys (all loaded keys valid except the tail,
// masked by position >= nv). bf16x3 tensor cores + ldmatrix.
// ---------------------------------------------------------------------------
#define ASTR 36
#define ATTN_SMEM ((2 * 128 * ASTR + 4 * 64 * ASTR) * 4)

__global__ __launch_bounds__(256, 2)
void attn_mma(float* __restrict__ out)
{
    extern __shared__ uint32_t smw[];
    uint32_t* Qh = smw;                    // [128][ASTR] bf16x2 hi
    uint32_t* Ql = Qh + 128 * ASTR;
    uint32_t* Kh = Ql + 128 * ASTR;        // [64 key][ASTR]
    uint32_t* Kl = Kh + 64 * ASTR;
    uint32_t* Vh = Kl + 64 * ASTR;         // [64 key][ASTR] (key-major)
    uint32_t* Vl = Vh + 64 * ASTR;

    const int tid  = threadIdx.x;
    const int lane = tid & 31;
    const int w    = tid >> 5;
    const int tig  = lane & 3;
    const int wm   = w * 16;
    const int q0   = blockIdx.x << 7;
    const int h    = blockIdx.y;
    const int b    = blockIdx.z;

    const float* qb = g_q + (size_t)b * SLEN * DMODEL + h * DHEAD;
    const float* kb = g_k + (size_t)b * SLEN * DMODEL + h * DHEAD;
    const float* vb = g_v + (size_t)b * SLEN * DMODEL + h * DHEAD;
    const int    nvb   = g_nv[b];
    const int    ntile = (nvb + 63) >> 6;

    const int lane15  = lane & 15;
    const int halfsel = (lane >> 4) & 1;
    const int krow    = (lane & 7) + ((lane & 16) >> 1);
    const int kcol    = (lane & 8) >> 1;

    const uint32_t qa = sptr(Qh) + ((wm + lane15) * ASTR + halfsel * 4) * 4;
    const uint32_t ka = sptr(Kh) + (krow * ASTR + kcol) * 4;
    const uint32_t va = sptr(Vh) + (lane15 * ASTR + halfsel * 4) * 4;
    const uint32_t QLO = 128 * ASTR * 4;
    const uint32_t KLO = 64 * ASTR * 4;
    const uint32_t VLO = 64 * ASTR * 4;

    for (int i = tid; i < 2048; i += 256) {
        const int r = i >> 4, d = (i & 15) << 2;
        const float4 v = *(const float4*)(qb + (size_t)(q0 + r) * DMODEL + d);
        uint32_t h0, l0, h1, l1;
        split2(v.x, v.y, h0, l0);
        split2(v.z, v.w, h1, l1);
        *(uint2*)&Qh[r * ASTR + (d >> 1)] = make_uint2(h0, h1);
        *(uint2*)&Ql[r * ASTR + (d >> 1)] = make_uint2(l0, l1);
    }

    float O[8][4];
#pragma unroll
    for (int j = 0; j < 8; j++)
#pragma unroll
        for (int r = 0; r < 4; r++) O[j][r] = 0.f;
    float mrow0 = -1e30f, mrow1 = -1e30f, lrow0 = 0.f, lrow1 = 0.f;

    const unsigned FULL = 0xffffffffu;

    __syncthreads();

    for (int t = 0; t < ntile; t++) {
        const int k0 = t << 6;
        // ---- fill K and V (packed, key-major), split bf16
        for (int i = tid; i < 1024; i += 256) {
            const int r = i >> 4, d = (i & 15) << 2;
            const size_t gg = (size_t)(k0 + r) * DMODEL + d;
            const float4 kv = *(const float4*)(kb + gg);
            uint32_t h0, l0, h1, l1;
            split2(kv.x, kv.y, h0, l0);
            split2(kv.z, kv.w, h1, l1);
            *(uint2*)&Kh[r * ASTR + (d >> 1)] = make_uint2(h0, h1);
            *(uint2*)&Kl[r * ASTR + (d >> 1)] = make_uint2(l0, l1);
            const float4 vv = *(const float4*)(vb + gg);
            split2(vv.x, vv.y, h0, l0);
            split2(vv.z, vv.w, h1, l1);
            *(uint2*)&Vh[r * ASTR + (d >> 1)] = make_uint2(h0, h1);
            *(uint2*)&Vl[r * ASTR + (d >> 1)] = make_uint2(l0, l1);
        }
        __syncthreads();

        // ---- S = Q @ K^T (bf16x3, ldmatrix frags)
        float S[8][4];
#pragma unroll
        for (int j = 0; j < 8; j++)
#pragma unroll
            for (int r = 0; r < 4; r++) S[j][r] = 0.f;

#pragma unroll
        for (int ks = 0; ks < 4; ks++) {
            uint32_t ah[4], al[4];
            ldsm4(ah, qa + ks * 32);
            ldsm4(al, qa + ks * 32 + QLO);
#pragma unroll
            for (int jp = 0; jp < 4; jp++) {
                uint32_t bh[4], bl[4];
                const uint32_t kaddr = ka + jp * 16 * ASTR * 4 + ks * 32;
                ldsm4(bh, kaddr);
                ldsm4(bl, kaddr + KLO);
                mma16(S[2 * jp], ah, bh);         mma16(S[2 * jp], ah, bl);
                mma16(S[2 * jp], al, bh);
                mma16(S[2 * jp + 1], ah, bh + 2); mma16(S[2 * jp + 1], ah, bl + 2);
                mma16(S[2 * jp + 1], al, bh + 2);
            }
        }

        // ---- scale + tail mask (position >= nv), registers only
        float mx0 = -1e30f, mx1 = -1e30f;
#pragma unroll
        for (int j = 0; j < 8; j++) {
            const int c = k0 + j * 8 + 2 * tig;
            const bool d0 = (c >= nvb);
            const bool d1 = (c + 1 >= nvb);
            S[j][0] = d0 ? -1e9f : S[j][0] * ATT_SCALE;
            S[j][1] = d1 ? -1e9f : S[j][1] * ATT_SCALE;
            S[j][2] = d0 ? -1e9f : S[j][2] * ATT_SCALE;
            S[j][3] = d1 ? -1e9f : S[j][3] * ATT_SCALE;
            mx0 = fmaxf(mx0, fmaxf(S[j][0], S[j][1]));
            mx1 = fmaxf(mx1, fmaxf(S[j][2], S[j][3]));
        }
        mx0 = fmaxf(mx0, __shfl_xor_sync(FULL, mx0, 1));
        mx0 = fmaxf(mx0, __shfl_xor_sync(FULL, mx0, 2));
        mx1 = fmaxf(mx1, __shfl_xor_sync(FULL, mx1, 1));
        mx1 = fmaxf(mx1, __shfl_xor_sync(FULL, mx1, 2));

        const float mnew0 = fmaxf(mrow0, mx0);
        const float mnew1 = fmaxf(mrow1, mx1);
        const float fac0  = __expf(mrow0 - mnew0);
        const float fac1  = __expf(mrow1 - mnew1);

        float sum0 = 0.f, sum1 = 0.f;
#pragma unroll
        for (int j = 0; j < 8; j++) {
            S[j][0] = __expf(S[j][0] - mnew0);
            S[j][1] = __expf(S[j][1] - mnew0);
            S[j][2] = __expf(S[j][2] - mnew1);
            S[j][3] = __expf(S[j][3] - mnew1);
            sum0 += S[j][0] + S[j][1];
            sum1 += S[j][2] + S[j][3];
        }
        sum0 += __shfl_xor_sync(FULL, sum0, 1);
        sum0 += __shfl_xor_sync(FULL, sum0, 2);
        sum1 += __shfl_xor_sync(FULL, sum1, 1);
        sum1 += __shfl_xor_sync(FULL, sum1, 2);

        lrow0 = lrow0 * fac0 + sum0;
        lrow1 = lrow1 * fac1 + sum1;
        mrow0 = mnew0;
        mrow1 = mnew1;

#pragma unroll
        for (int j = 0; j < 8; j++) {
            O[j][0] *= fac0; O[j][1] *= fac0;
            O[j][2] *= fac1; O[j][3] *= fac1;
        }

        // ---- O += P @ V (P in-register cvt; V via ldmatrix.trans)
#pragma unroll
        for (int ks = 0; ks < 4; ks++) {
            uint32_t ah[4], al[4];
            split2(S[2 * ks][0],     S[2 * ks][1],     ah[0], al[0]);
            split2(S[2 * ks][2],     S[2 * ks][3],     ah[1], al[1]);
            split2(S[2 * ks + 1][0], S[2 * ks + 1][1], ah[2], al[2]);
            split2(S[2 * ks + 1][2], S[2 * ks + 1][3], ah[3], al[3]);
#pragma unroll
            for (int jnp = 0; jnp < 4; jnp++) {
                uint32_t bh[4], bl[4];
                const uint32_t vaddr = va + ks * 16 * ASTR * 4 + jnp * 32;
                ldsm4t(bh, vaddr);
                ldsm4t(bl, vaddr + VLO);
                mma16(O[2 * jnp], ah, bh);         mma16(O[2 * jnp], ah, bl);
                mma16(O[2 * jnp], al, bh);
                mma16(O[2 * jnp + 1], ah, bh + 2); mma16(O[2 * jnp + 1], ah, bl + 2);
                mma16(O[2 * jnp + 1], al, bh + 2);
            }
        }
        __syncthreads();
    }

    // ---- epilogue: normalize + store (float2)
    const int g2 = (lane >> 2);
    const float inv0 = 1.f / lrow0;
    const float inv1 = 1.f / lrow1;
    const int row0 = q0 + wm + g2;
#pragma unroll
    for (int jn = 0; jn < 8; jn++) {
        const int col = h * DHEAD + jn * 8 + 2 * tig;
        float2 v0, v1;
        v0.x = O[jn][0] * inv0; v0.y = O[jn][1] * inv0;
        v1.x = O[jn][2] * inv1; v1.y = O[jn][3] * inv1;
        *(float2*)(out + ((size_t)b * SLEN + row0) * DMODEL + col)     = v0;
        *(float2*)(out + ((size_t)b * SLEN + row0 + 8) * DMODEL + col) = v1;
    }
}

// ---------------------------------------------------------------------------
extern "C" void kernel_launch(void* const* d_in, const int* in_sizes, int n_in,
                              void* d_out, int out_size)
{
    const float* Q    = (const float*)d_in[0];
    const float* K    = (const float*)d_in[1];
    const float* V    = (const float*)d_in[2];
    const int*   mask = (const int*)d_in[3];
    const float* Wq   = (const float*)d_in[4];
    const float* bq   = (const float*)d_in[5];
    const float* Wk   = (const float*)d_in[6];
    const float* bk   = (const float*)d_in[7];
    const float* Wv   = (const float*)d_in[8];
    const float* bv   = (const float*)d_in[9];
    float* out = (float*)d_out;

    float *qd, *kd, *vd;
    cudaGetSymbolAddress((void**)&qd, g_q);
    cudaGetSymbolAddress((void**)&kd, g_k);
    cudaGetSymbolAddress((void**)&vd, g_v);

    compact_mask<<<BATCH, 256>>>(mask);

    cudaFuncSetAttribute(proj_mma, cudaFuncAttributeMaxDynamicSharedMemorySize,
                         PROJ_SMEM);
    const dim3 pgrid(DMODEL / 128, (BATCH * SLEN) / 128, 3);
    proj_mma<<<pgrid, 256, PROJ_SMEM>>>(Q, K, V, Wq, Wk, Wv, bq, bk, bv,
                                        qd, kd, vd);

    cudaFuncSetAttribute(attn_mma, cudaFuncAttributeMaxDynamicSharedMemorySize,
                         ATTN_SMEM);
    const dim3 agrid(SLEN / 128, NHEAD, BATCH);
    attn_mma<<<agrid, 256, ATTN_SMEM>>>(out);
}

// round 9
// speedup vs baseline: 6.0459x; 1.1206x over previous
#include <cuda_runtime.h>
#include <cuda_bf16.h>
#include <math.h>
#include <stdint.h>

#define BATCH  4
#define SLEN   2048
#define DMODEL 1024
#define NHEAD  16
#define DHEAD  64
#define ATT_SCALE 0.125f   // 1/sqrt(64)

// ---------------------------------------------------------------------------
// Device scratch (no cudaMalloc allowed). All projected tensors stored as
// pre-split bf16 hi/lo pairs; W^T likewise.
// ---------------------------------------------------------------------------
#define NTOK (BATCH * SLEN * DMODEL)
__device__ __nv_bfloat16 g_qh[NTOK], g_ql[NTOK];
__device__ __nv_bfloat16 g_kh[NTOK], g_kl[NTOK];
__device__ __nv_bfloat16 g_vh[NTOK], g_vl[NTOK];
__device__ __nv_bfloat16 g_wth[3 * DMODEL * DMODEL], g_wtl[3 * DMODEL * DMODEL];
__device__ int g_idx[BATCH * SLEN];
__device__ int g_nv[BATCH];

// ---------------------------------------------------------------------------
// Helpers
// ---------------------------------------------------------------------------
__device__ __forceinline__ void mma16(float c[4], const uint32_t a[4],
                                      const uint32_t b[2]) {
    asm volatile(
        "mma.sync.aligned.m16n8k16.row.col.f32.bf16.bf16.f32 "
        "{%0,%1,%2,%3}, {%4,%5,%6,%7}, {%8,%9}, {%0,%1,%2,%3};"
        : "+f"(c[0]), "+f"(c[1]), "+f"(c[2]), "+f"(c[3])
        : "r"(a[0]), "r"(a[1]), "r"(a[2]), "r"(a[3]),
          "r"(b[0]), "r"(b[1]));
}

__device__ __forceinline__ void ldsm4(uint32_t r[4], uint32_t addr) {
    asm volatile(
        "ldmatrix.sync.aligned.m8n8.x4.shared.b16 {%0,%1,%2,%3}, [%4];"
        : "=r"(r[0]), "=r"(r[1]), "=r"(r[2]), "=r"(r[3]) : "r"(addr));
}

__device__ __forceinline__ void ldsm4t(uint32_t r[4], uint32_t addr) {
    asm volatile(
        "ldmatrix.sync.aligned.m8n8.x4.trans.shared.b16 {%0,%1,%2,%3}, [%4];"
        : "=r"(r[0]), "=r"(r[1]), "=r"(r[2]), "=r"(r[3]) : "r"(addr));
}

__device__ __forceinline__ uint32_t sptr(const void* p) {
    return (uint32_t)__cvta_generic_to_shared(p);
}

__device__ __forceinline__ void cpa16(uint32_t s, const void* g) {
    asm volatile("cp.async.cg.shared.global [%0], [%1], 16;" :: "r"(s), "l"(g));
}
#define CP_COMMIT() asm volatile("cp.async.commit_group;" ::: "memory")
#define CP_WAIT0()  asm volatile("cp.async.wait_group 0;" ::: "memory")

__device__ __forceinline__ void split2(float x0, float x1, uint32_t& h,
                                       uint32_t& l) {
    __nv_bfloat162 hb = __floats2bfloat162_rn(x0, x1);
    const float2 hf = __bfloat1622float2(hb);
    __nv_bfloat162 lb = __floats2bfloat162_rn(x0 - hf.x, x1 - hf.y);
    h = *reinterpret_cast<uint32_t*>(&hb);
    l = *reinterpret_cast<uint32_t*>(&lb);
}

// ---------------------------------------------------------------------------
// Mask compaction: per batch, prefix-scan the key-padding mask.
// ---------------------------------------------------------------------------
__global__ __launch_bounds__(256)
void compact_mask(const int* __restrict__ mask)
{
    __shared__ int part[256];
    const int b   = blockIdx.x;
    const int tid = threadIdx.x;
    const int* mb = mask + b * SLEN;

    int loc[8];
    int cnt = 0;
#pragma unroll
    for (int e = 0; e < 8; e++) {
        loc[e] = cnt;
        cnt += (mb[tid * 8 + e] != 0);
    }
    part[tid] = cnt;
    __syncthreads();
#pragma unroll
    for (int off = 1; off < 256; off <<= 1) {
        const int v = (tid >= off) ? part[tid - off] : 0;
        __syncthreads();
        part[tid] += v;
        __syncthreads();
    }
    const int excl = part[tid] - cnt;
#pragma unroll
    for (int e = 0; e < 8; e++) {
        if (mb[tid * 8 + e] != 0)
            g_idx[b * SLEN + excl + loc[e]] = tid * 8 + e;
    }
    const int total = part[255];
    if (tid == 0) g_nv[b] = total;
    __syncthreads();
    for (int j = total + tid; j < SLEN; j += 256)
        g_idx[b * SLEN + j] = 0;
}

// ---------------------------------------------------------------------------
// W^T prep: transpose + bf16 hi/lo split all three weight matrices.
// ---------------------------------------------------------------------------
__global__ __launch_bounds__(256)
void wT_split(const float* __restrict__ W0, const float* __restrict__ W1,
              const float* __restrict__ W2)
{
    __shared__ float t[32][33];
    const int z  = blockIdx.z;
    const float* W = (z == 0) ? W0 : (z == 1) ? W1 : W2;
    const int x  = blockIdx.x * 32 + threadIdx.x;   // n index
    const int y0 = blockIdx.y * 32;                 // k base
#pragma unroll
    for (int i = threadIdx.y; i < 32; i += 8)
        t[i][threadIdx.x] = W[(size_t)(y0 + i) * DMODEL + x];
    __syncthreads();
    const int ko = y0 + threadIdx.x;
    const int no = blockIdx.x * 32;
    __nv_bfloat16* th = g_wth + (size_t)z * DMODEL * DMODEL;
    __nv_bfloat16* tl = g_wtl + (size_t)z * DMODEL * DMODEL;
#pragma unroll
    for (int i = threadIdx.y; i < 32; i += 8) {
        const float v = t[threadIdx.x][i];
        const __nv_bfloat16 h = __float2bfloat16(v);
        th[(size_t)(no + i) * DMODEL + ko] = h;
        tl[(size_t)(no + i) * DMODEL + ko] =
            __float2bfloat16(v - __bfloat162float(h));
    }
}

// ---------------------------------------------------------------------------
// Fused projection GEMMs. z=0: Q (direct rows). z=1/2: K/V with row gather
// through g_idx into PACKED bf16 hi/lo outputs; tiles beyond nv[b] exit.
// B tiles are pure cp.async copies of pre-split W^T.
// ---------------------------------------------------------------------------
#define PSTR 20
#define PROJ_SMEM (4 * 128 * PSTR * 4)   // 40960 bytes

__global__ __launch_bounds__(256, 2)
void proj_mma(const float* __restrict__ X0, const float* __restrict__ X1,
              const float* __restrict__ X2,
              const float* __restrict__ b0, const float* __restrict__ b1,
              const float* __restrict__ b2)
{
    extern __shared__ uint32_t smw[];
    uint32_t* Ah = smw;
    uint32_t* Al = Ah + 128 * PSTR;
    uint32_t* Bh = Al + 128 * PSTR;
    uint32_t* Bl = Bh + 128 * PSTR;

    const int z = blockIdx.z;
    const float* X    = (z == 0) ? X0 : (z == 1) ? X1 : X2;
    const float* bias = (z == 0) ? b0 : (z == 1) ? b1 : b2;
    __nv_bfloat16* Yh = (z == 0) ? g_qh : (z == 1) ? g_kh : g_vh;
    __nv_bfloat16* Yl = (z == 0) ? g_ql : (z == 1) ? g_kl : g_vl;
    const __nv_bfloat16* WTh = g_wth + (size_t)z * DMODEL * DMODEL;
    const __nv_bfloat16* WTl = g_wtl + (size_t)z * DMODEL * DMODEL;

    const int m0   = blockIdx.y * 128;
    const int n0   = blockIdx.x * 128;
    const int bb   = m0 >> 11;
    const int mloc = m0 & 2047;

    const int nvb = (z == 0) ? SLEN : g_nv[bb];
    if (mloc >= nvb) return;
    const int* idxb = g_idx + bb * SLEN;

    const int tid  = threadIdx.x;
    const int lane = tid & 31;
    const int w    = tid >> 5;
    const int g    = lane >> 2;
    const int tig  = lane & 3;
    const int wm   = (w >> 2) * 64;
    const int wn   = (w & 3) * 32;

    const int lane15  = lane & 15;
    const int halfsel = (lane >> 4) & 1;
    const int krow    = (lane & 7) + ((lane & 16) >> 1);
    const int kcol    = (lane & 8) >> 1;

    const uint32_t pa = sptr(Ah) + ((wm + lane15) * PSTR + halfsel * 4) * 4;
    const uint32_t pb = sptr(Bh) + ((wn + krow) * PSTR + kcol) * 4;
    const uint32_t ALO = 128 * PSTR * 4;
    const uint32_t BLO = 128 * PSTR * 4;

    int srow[4];
#pragma unroll
    for (int it = 0; it < 4; it++) {
        const int r = (tid + it * 256) >> 3;
        if (z == 0) srow[it] = m0 + r;
        else {
            const int j = mloc + r;
            srow[it] = (bb << 11) + ((j < nvb) ? idxb[j] : idxb[0]);
        }
    }

    // B-chunk addressing (2 iters x 16B per array)
    const uint32_t sBh = sptr(Bh), sBl = sptr(Bl);

    float acc[4][4][4];
#pragma unroll
    for (int i = 0; i < 4; i++)
#pragma unroll
        for (int j = 0; j < 4; j++)
#pragma unroll
            for (int r = 0; r < 4; r++) acc[i][j][r] = 0.f;

    for (int k0 = 0; k0 < DMODEL; k0 += 32) {
        // ---- A tile: fp32 X rows, split to bf16 hi/lo
#pragma unroll
        for (int it = 0; it < 4; it++) {
            const int idx = tid + it * 256;
            const int r = idx >> 3, c = (idx & 7) << 2;
            const float4 v = *(const float4*)(X + (size_t)srow[it] * DMODEL + k0 + c);
            uint32_t h0, l0, h1, l1;
            split2(v.x, v.y, h0, l0);
            split2(v.z, v.w, h1, l1);
            *(uint2*)&Ah[r * PSTR + (c >> 1)] = make_uint2(h0, h1);
            *(uint2*)&Al[r * PSTR + (c >> 1)] = make_uint2(l0, l1);
        }
        // ---- B tile: pure cp.async copy of pre-split W^T
#pragma unroll
        for (int it = 0; it < 2; it++) {
            const int idx = tid + it * 256;
            const int n = idx >> 2, ch = idx & 3;
            const size_t gg = (size_t)(n0 + n) * DMODEL + k0 + ch * 8;
            const uint32_t sm = (n * PSTR + ch * 4) * 4;
            cpa16(sBh + sm, WTh + gg);
            cpa16(sBl + sm, WTl + gg);
        }
        CP_COMMIT();
        CP_WAIT0();
        __syncthreads();

#pragma unroll
        for (int ks = 0; ks < 2; ks++) {
            uint32_t bh0[4], bl0[4], bh1[4], bl1[4];
            ldsm4(bh0, pb + ks * 32);
            ldsm4(bl0, pb + ks * 32 + BLO);
            ldsm4(bh1, pb + 16 * PSTR * 4 + ks * 32);
            ldsm4(bl1, pb + 16 * PSTR * 4 + ks * 32 + BLO);
#pragma unroll
            for (int i = 0; i < 4; i++) {
                uint32_t ah[4], al[4];
                ldsm4(ah, pa + i * 16 * PSTR * 4 + ks * 32);
                ldsm4(al, pa + i * 16 * PSTR * 4 + ks * 32 + ALO);
                mma16(acc[i][0], ah, bh0);     mma16(acc[i][0], ah, bl0);
                mma16(acc[i][0], al, bh0);
                mma16(acc[i][1], ah, bh0 + 2); mma16(acc[i][1], ah, bl0 + 2);
                mma16(acc[i][1], al, bh0 + 2);
                mma16(acc[i][2], ah, bh1);     mma16(acc[i][2], ah, bl1);
                mma16(acc[i][2], al, bh1);
                mma16(acc[i][3], ah, bh1 + 2); mma16(acc[i][3], ah, bl1 + 2);
                mma16(acc[i][3], al, bh1 + 2);
            }
        }
        __syncthreads();
    }

    // ---- epilogue: +bias, split to bf16 hi/lo, store packed words
#pragma unroll
    for (int j = 0; j < 4; j++) {
        const int col = n0 + wn + j * 8 + 2 * tig;
        const float bx = bias[col], by = bias[col + 1];
#pragma unroll
        for (int i = 0; i < 4; i++) {
            const int r0 = m0 + wm + i * 16 + g;
            uint32_t h0, l0, h1, l1;
            split2(acc[i][j][0] + bx, acc[i][j][1] + by, h0, l0);
            split2(acc[i][j][2] + bx, acc[i][j][3] + by, h1, l1);
            *(uint32_t*)&Yh[(size_t)r0 * DMODEL + col]       = h0;
            *(uint32_t*)&Yl[(size_t)r0 * DMODEL + col]       = l0;
            *(uint32_t*)&Yh[(size_t)(r0 + 8) * DMODEL + col] = h1;
            *(uint32_t*)&Yl[(size_t)(r0 + 8) * DMODEL + col] = l1;
        }
    }
}

// ---------------------------------------------------------------------------
// Flash attention over PACKED pre-split bf16 keys. All fills are cp.async
// copies; only softmax math runs on the ALU/SFU.
// ---------------------------------------------------------------------------
#define ASTR 36
#define ATTN_SMEM ((2 * 128 * ASTR + 4 * 64 * ASTR) * 4)

__global__ __launch_bounds__(256, 2)
void attn_mma(float* __restrict__ out)
{
    extern __shared__ uint32_t smw[];
    uint32_t* Qh = smw;                    // [128][ASTR]
    uint32_t* Ql = Qh + 128 * ASTR;
    uint32_t* Kh = Ql + 128 * ASTR;        // [64 key][ASTR]
    uint32_t* Kl = Kh + 64 * ASTR;
    uint32_t* Vh = Kl + 64 * ASTR;         // [64 key][ASTR] (key-major)
    uint32_t* Vl = Vh + 64 * ASTR;

    const int tid  = threadIdx.x;
    const int lane = tid & 31;
    const int w    = tid >> 5;
    const int tig  = lane & 3;
    const int wm   = w * 16;
    const int q0   = blockIdx.x << 7;
    const int h    = blockIdx.y;
    const int b    = blockIdx.z;

    const size_t base = (size_t)b * SLEN * DMODEL + h * DHEAD;
    const __nv_bfloat16* qhg = g_qh + base;
    const __nv_bfloat16* qlg = g_ql + base;
    const __nv_bfloat16* khg = g_kh + base;
    const __nv_bfloat16* klg = g_kl + base;
    const __nv_bfloat16* vhg = g_vh + base;
    const __nv_bfloat16* vlg = g_vl + base;
    const int nvb   = g_nv[b];
    const int ntile = (nvb + 63) >> 6;

    const int lane15  = lane & 15;
    const int halfsel = (lane >> 4) & 1;
    const int krow    = (lane & 7) + ((lane & 16) >> 1);
    const int kcol    = (lane & 8) >> 1;

    const uint32_t qa = sptr(Qh) + ((wm + lane15) * ASTR + halfsel * 4) * 4;
    const uint32_t ka = sptr(Kh) + (krow * ASTR + kcol) * 4;
    const uint32_t va = sptr(Vh) + (lane15 * ASTR + halfsel * 4) * 4;
    const uint32_t QLO = 128 * ASTR * 4;
    const uint32_t KLO = 64 * ASTR * 4;
    const uint32_t VLO = 64 * ASTR * 4;

    const uint32_t sQh = sptr(Qh), sQl = sptr(Ql);
    const uint32_t sKh = sptr(Kh), sKl = sptr(Kl);
    const uint32_t sVh = sptr(Vh), sVl = sptr(Vl);

    // ---- Q tile: pure cp.async copy (128 rows x 64 dims, hi+lo)
#pragma unroll
    for (int it = 0; it < 4; it++) {
        const int idx = tid + it * 256;
        const int r = idx >> 3, ch = idx & 7;
        const size_t gg = (size_t)(q0 + r) * DMODEL + ch * 8;
        const uint32_t sm = (r * ASTR + ch * 4) * 4;
        cpa16(sQh + sm, qhg + gg);
        cpa16(sQl + sm, qlg + gg);
    }
    CP_COMMIT();

    float O[8][4];
#pragma unroll
    for (int j = 0; j < 8; j++)
#pragma unroll
        for (int r = 0; r < 4; r++) O[j][r] = 0.f;
    float mrow0 = -1e30f, mrow1 = -1e30f, lrow0 = 0.f, lrow1 = 0.f;

    const unsigned FULL = 0xffffffffu;

    CP_WAIT0();
    __syncthreads();

    for (int t = 0; t < ntile; t++) {
        const int k0 = t << 6;
        // ---- K/V fill: pure cp.async copies (64 rows x 64 dims x 4 arrays)
#pragma unroll
        for (int it = 0; it < 2; it++) {
            const int idx = tid + it * 256;
            const int r = idx >> 3, ch = idx & 7;
            const size_t gg = (size_t)(k0 + r) * DMODEL + ch * 8;
            const uint32_t sm = (r * ASTR + ch * 4) * 4;
            cpa16(sKh + sm, khg + gg);
            cpa16(sKl + sm, klg + gg);
            cpa16(sVh + sm, vhg + gg);
            cpa16(sVl + sm, vlg + gg);
        }
        CP_COMMIT();
        CP_WAIT0();
        __syncthreads();

        // ---- S = Q @ K^T (bf16x3, ldmatrix frags)
        float S[8][4];
#pragma unroll
        for (int j = 0; j < 8; j++)
#pragma unroll
            for (int r = 0; r < 4; r++) S[j][r] = 0.f;

#pragma unroll
        for (int ks = 0; ks < 4; ks++) {
            uint32_t ah[4], al[4];
            ldsm4(ah, qa + ks * 32);
            ldsm4(al, qa + ks * 32 + QLO);
#pragma unroll
            for (int jp = 0; jp < 4; jp++) {
                uint32_t bh[4], bl[4];
                const uint32_t kaddr = ka + jp * 16 * ASTR * 4 + ks * 32;
                ldsm4(bh, kaddr);
                ldsm4(bl, kaddr + KLO);
                mma16(S[2 * jp], ah, bh);         mma16(S[2 * jp], ah, bl);
                mma16(S[2 * jp], al, bh);
                mma16(S[2 * jp + 1], ah, bh + 2); mma16(S[2 * jp + 1], ah, bl + 2);
                mma16(S[2 * jp + 1], al, bh + 2);
            }
        }

        // ---- scale + tail mask (position >= nv)
        float mx0 = -1e30f, mx1 = -1e30f;
#pragma unroll
        for (int j = 0; j < 8; j++) {
            const int c = k0 + j * 8 + 2 * tig;
            const bool d0 = (c >= nvb);
            const bool d1 = (c + 1 >= nvb);
            S[j][0] = d0 ? -1e9f : S[j][0] * ATT_SCALE;
            S[j][1] = d1 ? -1e9f : S[j][1] * ATT_SCALE;
            S[j][2] = d0 ? -1e9f : S[j][2] * ATT_SCALE;
            S[j][3] = d1 ? -1e9f : S[j][3] * ATT_SCALE;
            mx0 = fmaxf(mx0, fmaxf(S[j][0], S[j][1]));
            mx1 = fmaxf(mx1, fmaxf(S[j][2], S[j][3]));
        }
        mx0 = fmaxf(mx0, __shfl_xor_sync(FULL, mx0, 1));
        mx0 = fmaxf(mx0, __shfl_xor_sync(FULL, mx0, 2));
        mx1 = fmaxf(mx1, __shfl_xor_sync(FULL, mx1, 1));
        mx1 = fmaxf(mx1, __shfl_xor_sync(FULL, mx1, 2));

        const float mnew0 = fmaxf(mrow0, mx0);
        const float mnew1 = fmaxf(mrow1, mx1);
        const float fac0  = __expf(mrow0 - mnew0);
        const float fac1  = __expf(mrow1 - mnew1);

        float sum0 = 0.f, sum1 = 0.f;
#pragma unroll
        for (int j = 0; j < 8; j++) {
            S[j][0] = __expf(S[j][0] - mnew0);
            S[j][1] = __expf(S[j][1] - mnew0);
            S[j][2] = __expf(S[j][2] - mnew1);
            S[j][3] = __expf(S[j][3] - mnew1);
            sum0 += S[j][0] + S[j][1];
            sum1 += S[j][2] + S[j][3];
        }
        sum0 += __shfl_xor_sync(FULL, sum0, 1);
        sum0 += __shfl_xor_sync(FULL, sum0, 2);
        sum1 += __shfl_xor_sync(FULL, sum1, 1);
        sum1 += __shfl_xor_sync(FULL, sum1, 2);

        lrow0 = lrow0 * fac0 + sum0;
        lrow1 = lrow1 * fac1 + sum1;
        mrow0 = mnew0;
        mrow1 = mnew1;

#pragma unroll
        for (int j = 0; j < 8; j++) {
            O[j][0] *= fac0; O[j][1] *= fac0;
            O[j][2] *= fac1; O[j][3] *= fac1;
        }

        // ---- O += P @ V (P in-register cvt; V via ldmatrix.trans)
#pragma unroll
        for (int ks = 0; ks < 4; ks++) {
            uint32_t ah[4], al[4];
            split2(S[2 * ks][0],     S[2 * ks][1],     ah[0], al[0]);
            split2(S[2 * ks][2],     S[2 * ks][3],     ah[1], al[1]);
            split2(S[2 * ks + 1][0], S[2 * ks + 1][1], ah[2], al[2]);
            split2(S[2 * ks + 1][2], S[2 * ks + 1][3], ah[3], al[3]);
#pragma unroll
            for (int jnp = 0; jnp < 4; jnp++) {
                uint32_t bh[4], bl[4];
                const uint32_t vaddr = va + ks * 16 * ASTR * 4 + jnp * 32;
                ldsm4t(bh, vaddr);
                ldsm4t(bl, vaddr + VLO);
                mma16(O[2 * jnp], ah, bh);         mma16(O[2 * jnp], ah, bl);
                mma16(O[2 * jnp], al, bh);
                mma16(O[2 * jnp + 1], ah, bh + 2); mma16(O[2 * jnp + 1], ah, bl + 2);
                mma16(O[2 * jnp + 1], al, bh + 2);
            }
        }
        __syncthreads();
    }

    // ---- epilogue: normalize + store (float2)
    const int g2 = (lane >> 2);
    const float inv0 = 1.f / lrow0;
    const float inv1 = 1.f / lrow1;
    const int row0 = q0 + wm + g2;
#pragma unroll
    for (int jn = 0; jn < 8; jn++) {
        const int col = h * DHEAD + jn * 8 + 2 * tig;
        float2 v0, v1;
        v0.x = O[jn][0] * inv0; v0.y = O[jn][1] * inv0;
        v1.x = O[jn][2] * inv1; v1.y = O[jn][3] * inv1;
        *(float2*)(out + ((size_t)b * SLEN + row0) * DMODEL + col)     = v0;
        *(float2*)(out + ((size_t)b * SLEN + row0 + 8) * DMODEL + col) = v1;
    }
}

// ---------------------------------------------------------------------------
extern "C" void kernel_launch(void* const* d_in, const int* in_sizes, int n_in,
                              void* d_out, int out_size)
{
    const float* Q    = (const float*)d_in[0];
    const float* K    = (const float*)d_in[1];
    const float* V    = (const float*)d_in[2];
    const int*   mask = (const int*)d_in[3];
    const float* Wq   = (const float*)d_in[4];
    const float* bq   = (const float*)d_in[5];
    const float* Wk   = (const float*)d_in[6];
    const float* bk   = (const float*)d_in[7];
    const float* Wv   = (const float*)d_in[8];
    const float* bv   = (const float*)d_in[9];
    float* out = (float*)d_out;

    compact_mask<<<BATCH, 256>>>(mask);

    const dim3 tgrid(DMODEL / 32, DMODEL / 32, 3);
    wT_split<<<tgrid, dim3(32, 8)>>>(Wq, Wk, Wv);

    cudaFuncSetAttribute(proj_mma, cudaFuncAttributeMaxDynamicSharedMemorySize,
                         PROJ_SMEM);
    const dim3 pgrid(DMODEL / 128, (BATCH * SLEN) / 128, 3);
    proj_mma<<<pgrid, 256, PROJ_SMEM>>>(Q, K, V, bq, bk, bv);

    cudaFuncSetAttribute(attn_mma, cudaFuncAttributeMaxDynamicSharedMemorySize,
                         ATTN_SMEM);
    const dim3 agrid(SLEN / 128, NHEAD, BATCH);
    attn_mma<<<agrid, 256, ATTN_SMEM>>>(out);
}